// round 14
// baseline (speedup 1.0000x reference)
#include <cuda_runtime.h>
#include <cuda_bf16.h>
#include <math.h>
#include <stdint.h>

// Problem constants
#define BB 16
#define SS 1024
#define DD 512
#define HH 4
#define NTHR 256

// CTA tile 128(M) x 256(N) x 32(K); 8 warps as 2(m) x 4(n), warp tile 64x64.
// smem per stage: A hi/lo 128x32 (80B rows, 10240 ea) + B hi/lo (20480 slot ea)
#define ST_SZ  61440
#define OFF_AH 0
#define OFF_AL 10240
#define OFF_BH 20480
#define OFF_BL 40960
#define SMEM_SZ (2 * ST_SZ)

#define STRA   80    // bytes per 32-bf16 smem row (+16 pad)
#define STRB   528   // bytes per 256-bf16 smem row (+16 pad), NN/trans B

// ---------------- device scratch ----------------
__device__ __align__(16) __nv_bfloat16 g_x_hi[(size_t)BB*SS*DD];
__device__ __align__(16) __nv_bfloat16 g_x_lo[(size_t)BB*SS*DD];
__device__ __align__(16) __nv_bfloat16 g_v_hi[(size_t)BB*SS*DD];
__device__ __align__(16) __nv_bfloat16 g_v_lo[(size_t)BB*SS*DD];
__device__ __align__(16) __nv_bfloat16 g_attn_hi[(size_t)BB*SS*SS];
__device__ __align__(16) __nv_bfloat16 g_attn_lo[(size_t)BB*SS*SS];
__device__ __align__(16) __nv_bfloat16 g_w_hi[(size_t)HH*DD*DD];
__device__ __align__(16) __nv_bfloat16 g_w_lo[(size_t)HH*DD*DD];
__device__ __align__(16) float g_norm2[HH * BB * SS];
__device__ int g_pad32[BB*(SS/32)];
__device__ int g_pad256[BB*(SS/256)];

// ---------------- PTX helpers (sm_80-level only; harness targets plain sm_103) ----
#define CPA16(s, g) asm volatile("cp.async.cg.shared.global [%0], [%1], 16;" :: "r"(s), "l"(g))
#define CP_COMMIT() asm volatile("cp.async.commit_group;" ::: "memory")
#define CP_WAIT1()  asm volatile("cp.async.wait_group 1;" ::: "memory")
#define CP_WAIT0()  asm volatile("cp.async.wait_group 0;" ::: "memory")

#define LDSMX4(r0, r1, r2, r3, a)                                              \
    asm volatile("ldmatrix.sync.aligned.m8n8.x4.shared.b16 {%0,%1,%2,%3}, [%4];" \
                 : "=r"(r0), "=r"(r1), "=r"(r2), "=r"(r3) : "r"(a))
#define LDSMX4T(r0, r1, r2, r3, a)                                             \
    asm volatile("ldmatrix.sync.aligned.m8n8.x4.trans.shared.b16 {%0,%1,%2,%3}, [%4];" \
                 : "=r"(r0), "=r"(r1), "=r"(r2), "=r"(r3) : "r"(a))

#define MMA16816(c, a, b0v, b1v)                                               \
    asm volatile(                                                              \
        "mma.sync.aligned.m16n8k16.row.col.f32.bf16.bf16.f32 "                 \
        "{%0,%1,%2,%3}, {%4,%5,%6,%7}, {%8,%9}, {%0,%1,%2,%3};"                \
        : "+f"((c)[0]), "+f"((c)[1]), "+f"((c)[2]), "+f"((c)[3])               \
        : "r"((a)[0]), "r"((a)[1]), "r"((a)[2]), "r"((a)[3]), "r"(b0v), "r"(b1v))

// ---------------- tile loaders (256 threads) ----------------
// A: 128 rows x 32 bf16 from row-major (ld2 = row stride bytes)
__device__ __forceinline__ void ldg_A(uint32_t dst, const char* src, size_t ld2, int kt) {
#pragma unroll
    for (int p = 0; p < 2; p++) {
        int i = threadIdx.x + p * NTHR;
        int row = i >> 2, seg = i & 3;
        CPA16(dst + row * STRA + seg * 16,
              src + (size_t)row * ld2 + (size_t)kt * 2 + seg * 16);
    }
}
// B NT: 256 rows x 32 bf16
__device__ __forceinline__ void ldg_B_nt(uint32_t dst, const char* src, size_t ld2, int kt) {
#pragma unroll
    for (int p = 0; p < 4; p++) {
        int i = threadIdx.x + p * NTHR;
        int row = i >> 2, seg = i & 3;
        CPA16(dst + row * STRA + seg * 16,
              src + (size_t)row * ld2 + (size_t)kt * 2 + seg * 16);
    }
}
// B NN (for trans-ldsm): 32 k-rows x 256 bf16 (512B used per row)
__device__ __forceinline__ void ldg_B_nn(uint32_t dst, const char* src, size_t ld2, int kt) {
#pragma unroll
    for (int p = 0; p < 4; p++) {
        int i = threadIdx.x + p * NTHR;
        int row = i >> 5, seg = i & 31;
        CPA16(dst + row * STRB + seg * 16,
              src + (size_t)(kt + row) * ld2 + seg * 16);
    }
}

// ---------------- warp MMA compute on one staged 128x256x32 chunk ------------
// Warp tile 64x64: mt 0..3 (16 rows each), nt 0..7 (8 cols each). C[4][8][4].
template <bool BT>
__device__ __forceinline__ void compute_chunk(uint32_t sbase, float (&C)[4][8][4]) {
    const int lane = threadIdx.x & 31;
    const int wid = threadIdx.x >> 5;
    const int wm = wid >> 2, wn = wid & 3;
#pragma unroll
    for (int ks = 0; ks < 2; ks++) {
        uint32_t ah[4][4], al[4][4];
#pragma unroll
        for (int mt = 0; mt < 4; mt++) {
            uint32_t ra = sbase + OFF_AH +
                (uint32_t)((wm * 64 + mt * 16 + (lane & 15)) * STRA + ks * 32 + (lane >> 4) * 16);
            LDSMX4(ah[mt][0], ah[mt][1], ah[mt][2], ah[mt][3], ra);
            ra += (OFF_AL - OFF_AH);
            LDSMX4(al[mt][0], al[mt][1], al[mt][2], al[mt][3], ra);
        }
#pragma unroll
        for (int nt2 = 0; nt2 < 4; nt2++) {
            uint32_t bh[4], bl[4];
            if (!BT) {
                uint32_t rb = sbase + OFF_BH +
                    (uint32_t)((wn * 64 + nt2 * 16 + (lane >> 4) * 8 + (lane & 7)) * STRA +
                               ks * 32 + ((lane >> 3) & 1) * 16);
                LDSMX4(bh[0], bh[1], bh[2], bh[3], rb);
                rb += (OFF_BL - OFF_BH);
                LDSMX4(bl[0], bl[1], bl[2], bl[3], rb);
            } else {
                uint32_t rb = sbase + OFF_BH +
                    (uint32_t)((ks * 16 + ((lane >> 3) & 1) * 8 + (lane & 7)) * STRB +
                               (wn * 64 + nt2 * 16) * 2 + (lane >> 4) * 16);
                LDSMX4T(bh[0], bh[1], bh[2], bh[3], rb);
                rb += (OFF_BL - OFF_BH);
                LDSMX4T(bl[0], bl[1], bl[2], bl[3], rb);
            }
#pragma unroll
            for (int mt = 0; mt < 4; mt++) {
#pragma unroll
                for (int j = 0; j < 2; j++) {
                    MMA16816(C[mt][nt2 * 2 + j], ah[mt], bh[j * 2], bh[j * 2 + 1]);
                    MMA16816(C[mt][nt2 * 2 + j], ah[mt], bl[j * 2], bl[j * 2 + 1]);
                    MMA16816(C[mt][nt2 * 2 + j], al[mt], bh[j * 2], bh[j * 2 + 1]);
                }
            }
        }
    }
}

__device__ __forceinline__ void zeroC(float (&C)[4][8][4]) {
#pragma unroll
    for (int a = 0; a < 4; a++)
#pragma unroll
        for (int b = 0; b < 8; b++)
#pragma unroll
            for (int c = 0; c < 4; c++) C[a][b][c] = 0.f;
}
__device__ __forceinline__ uint32_t packsplit_hi(float v0, float v1) {
    __nv_bfloat162 h = __floats2bfloat162_rn(v0, v1);
    return *(uint32_t*)&h;
}
__device__ __forceinline__ uint32_t packsplit_lo(float v0, float v1) {
    float r0 = v0 - __bfloat162float(__float2bfloat16(v0));
    float r1 = v1 - __bfloat162float(__float2bfloat16(v1));
    __nv_bfloat162 l = __floats2bfloat162_rn(r0, r1);
    return *(uint32_t*)&l;
}

// dense-K 16-chunk double-buffered mainloop (A 128x32, B 256x32 NT tiles)
__device__ __forceinline__ void mainloop_dense(uint32_t sb,
                                               const char* Ahi, const char* Alo,
                                               const char* Bhi, const char* Blo,
                                               size_t ld2, float (&C)[4][8][4]) {
    ldg_A(sb + OFF_AH, Ahi, ld2, 0); ldg_A(sb + OFF_AL, Alo, ld2, 0);
    ldg_B_nt(sb + OFF_BH, Bhi, ld2, 0); ldg_B_nt(sb + OFF_BL, Blo, ld2, 0);
    CP_COMMIT();
    ldg_A(sb + ST_SZ + OFF_AH, Ahi, ld2, 32); ldg_A(sb + ST_SZ + OFF_AL, Alo, ld2, 32);
    ldg_B_nt(sb + ST_SZ + OFF_BH, Bhi, ld2, 32); ldg_B_nt(sb + ST_SZ + OFF_BL, Blo, ld2, 32);
    CP_COMMIT();
    for (int ci = 0; ci < 16; ci++) {
        if (ci + 1 < 16) CP_WAIT1(); else CP_WAIT0();
        __syncthreads();
        compute_chunk<false>(sb + (ci & 1) * ST_SZ, C);
        __syncthreads();
        if (ci + 2 < 16) {
            uint32_t d = sb + (ci & 1) * ST_SZ;
            int kt = (ci + 2) * 32;
            ldg_A(d + OFF_AH, Ahi, ld2, kt); ldg_A(d + OFF_AL, Alo, ld2, kt);
            ldg_B_nt(d + OFF_BH, Bhi, ld2, kt); ldg_B_nt(d + OFF_BL, Blo, ld2, kt);
            CP_COMMIT();
        }
    }
}

// ---------------------------------------------------------------------------
// Fused K1+K3: blocks [0,512) qk tiles (128q x 256k), [512,768) v tiles (128 x 256).
// ---------------------------------------------------------------------------
__global__ __launch_bounds__(NTHR, 1) void k_qkv(int h, const int* __restrict__ et,
                                                 const float* __restrict__ bias) {
    extern __shared__ char smem[];
    const uint32_t sb = (uint32_t)__cvta_generic_to_shared(smem);
    const int flat = blockIdx.x;
    const int lane = threadIdx.x & 31, wid = threadIdx.x >> 5;
    const int wm = wid >> 2, wn = wid & 3;
    const size_t ld2 = (size_t)DD * 2;

    if (flat < 512) {
        // ---------------- qk path ----------------
        const int b = flat >> 5, qi = (flat >> 2) & 7, ki = flat & 3;
        const int q0 = qi * 128, k0 = ki * 256;
        if (k0 + 256 <= q0 && !g_pad256[b * 4 + ki]) return;  // all-zero tile
        const bool above = (k0 >= q0 + 128);                  // fully kept

        const char* Ahi = (const char*)g_x_hi + ((size_t)b * SS + q0) * DD * 2;
        const char* Alo = (const char*)g_x_lo + ((size_t)b * SS + q0) * DD * 2;
        const char* Bhi = (const char*)g_x_hi + ((size_t)b * SS + k0) * DD * 2;
        const char* Blo = (const char*)g_x_lo + ((size_t)b * SS + k0) * DD * 2;

        float C[4][8][4];
        zeroC(C);
        mainloop_dense(sb, Ahi, Alo, Bhi, Blo, ld2, C);

        const float invtemp = 0.04419417382415922f;  // 1/sqrt(512)
        float* norm2 = g_norm2 + (size_t)h * BB * SS;

        int kg[8]; bool pad0[8], pad1[8];
#pragma unroll
        for (int nt = 0; nt < 8; nt++) {
            kg[nt] = k0 + wn * 64 + nt * 8 + (lane & 3) * 2;
            pad0[nt] = (__ldg(et + b * SS + kg[nt]) == 0);
            pad1[nt] = (__ldg(et + b * SS + kg[nt] + 1) == 0);
        }
#pragma unroll
        for (int mt = 0; mt < 4; mt++) {
            const int r0 = wm * 64 + mt * 16 + (lane >> 2);
            const int qA = q0 + r0, qB = q0 + r0 + 8;
            float sqA = 0.f, sqB = 0.f;
#pragma unroll
            for (int nt = 0; nt < 8; nt++) {
                float v0 = C[mt][nt][0] * invtemp, v1 = C[mt][nt][1] * invtemp;
                float v2 = C[mt][nt][2] * invtemp, v3 = C[mt][nt][3] * invtemp;
                bool kA0 = above || (kg[nt] > qA) || pad0[nt];
                bool kA1 = above || (kg[nt] + 1 > qA) || pad1[nt];
                bool kB0 = above || (kg[nt] > qB) || pad0[nt];
                bool kB1 = above || (kg[nt] + 1 > qB) || pad1[nt];
                v0 = kA0 ? v0 : 0.f; v1 = kA1 ? v1 : 0.f;
                v2 = kB0 ? v2 : 0.f; v3 = kB1 ? v3 : 0.f;
                sqA = fmaf(v0, v0, fmaf(v1, v1, sqA));
                sqB = fmaf(v2, v2, fmaf(v3, v3, sqB));
                const size_t oA = ((size_t)b * SS + qA) * SS + kg[nt];
                const size_t oB = ((size_t)b * SS + qB) * SS + kg[nt];
                *(uint32_t*)(g_attn_hi + oA) = packsplit_hi(v0, v1);
                *(uint32_t*)(g_attn_lo + oA) = packsplit_lo(v0, v1);
                *(uint32_t*)(g_attn_hi + oB) = packsplit_hi(v2, v3);
                *(uint32_t*)(g_attn_lo + oB) = packsplit_lo(v2, v3);
            }
            sqA += __shfl_xor_sync(0xffffffffu, sqA, 1);
            sqA += __shfl_xor_sync(0xffffffffu, sqA, 2);
            sqB += __shfl_xor_sync(0xffffffffu, sqB, 1);
            sqB += __shfl_xor_sync(0xffffffffu, sqB, 2);
            if ((lane & 3) == 0) {
                atomicAdd(&norm2[b * SS + qA], sqA);
                atomicAdd(&norm2[b * SS + qB], sqB);
            }
        }
    } else {
        // ---------------- v path ----------------
        const int f = flat - 512;            // 0..255
        const int m0 = (f >> 1) * 128, n0 = (f & 1) * 256;

        const char* Ahi = (const char*)g_x_hi + (size_t)m0 * DD * 2;
        const char* Alo = (const char*)g_x_lo + (size_t)m0 * DD * 2;
        const char* Bhi = (const char*)g_w_hi + ((size_t)h * DD * DD + (size_t)n0 * DD) * 2;
        const char* Blo = (const char*)g_w_lo + ((size_t)h * DD * DD + (size_t)n0 * DD) * 2;

        float C[4][8][4];
        zeroC(C);
        mainloop_dense(sb, Ahi, Alo, Bhi, Blo, ld2, C);

        float b0[8], b1[8]; int col[8];
#pragma unroll
        for (int nt = 0; nt < 8; nt++) {
            col[nt] = n0 + wn * 64 + nt * 8 + (lane & 3) * 2;
            b0[nt] = __ldg(bias + col[nt]);
            b1[nt] = __ldg(bias + col[nt] + 1);
        }
#pragma unroll
        for (int mt = 0; mt < 4; mt++) {
            const int r0 = wm * 64 + mt * 16 + (lane >> 2);
            const size_t mA = (size_t)(m0 + r0), mB = mA + 8;
#pragma unroll
            for (int nt = 0; nt < 8; nt++) {
                float v0 = C[mt][nt][0] + b0[nt], v1 = C[mt][nt][1] + b1[nt];
                float v2 = C[mt][nt][2] + b0[nt], v3 = C[mt][nt][3] + b1[nt];
                v0 = (v0 > 0.f) ? v0 : expm1f(v0);
                v1 = (v1 > 0.f) ? v1 : expm1f(v1);
                v2 = (v2 > 0.f) ? v2 : expm1f(v2);
                v3 = (v3 > 0.f) ? v3 : expm1f(v3);
                const size_t oA = mA * DD + col[nt], oB = mB * DD + col[nt];
                *(uint32_t*)(g_v_hi + oA) = packsplit_hi(v0, v1);
                *(uint32_t*)(g_v_lo + oA) = packsplit_lo(v0, v1);
                *(uint32_t*)(g_v_hi + oB) = packsplit_hi(v2, v3);
                *(uint32_t*)(g_v_lo + oB) = packsplit_lo(v2, v3);
            }
        }
    }
}

// ---------------------------------------------------------------------------
// K4: xnew = invnorm * (attn · v); 128q x 256d per block; trans-ldsm B.
// ---------------------------------------------------------------------------
__global__ __launch_bounds__(NTHR, 1) void k_av(int h, float* __restrict__ out) {
    const int b = blockIdx.z, q0 = blockIdx.y * 128, n0 = blockIdx.x * 256;
    extern __shared__ char smem[];
    const uint32_t sb = (uint32_t)__cvta_generic_to_shared(smem);

    const char* Ahi = (const char*)g_attn_hi + ((size_t)b * SS + q0) * SS * 2;
    const char* Alo = (const char*)g_attn_lo + ((size_t)b * SS + q0) * SS * 2;
    const char* Bhi = (const char*)g_v_hi + ((size_t)b * SS * DD + n0) * 2;
    const char* Blo = (const char*)g_v_lo + ((size_t)b * SS * DD + n0) * 2;
    const size_t lda2 = (size_t)SS * 2, ldb2 = (size_t)DD * 2;
    const int* p32 = g_pad32 + b * (SS / 32);

    float C[4][8][4];
    zeroC(C);

    int kt_a = 0;
    while (kt_a + 32 <= q0 && !p32[kt_a >> 5]) kt_a += 32;
    int kt_b = kt_a + 32;
    while (kt_b < SS && kt_b + 32 <= q0 && !p32[kt_b >> 5]) kt_b += 32;

    ldg_A(sb + OFF_AH, Ahi, lda2, kt_a); ldg_A(sb + OFF_AL, Alo, lda2, kt_a);
    ldg_B_nn(sb + OFF_BH, Bhi, ldb2, kt_a); ldg_B_nn(sb + OFF_BL, Blo, ldb2, kt_a);
    CP_COMMIT();
    bool has_b = (kt_b < SS);
    if (has_b) {
        ldg_A(sb + ST_SZ + OFF_AH, Ahi, lda2, kt_b); ldg_A(sb + ST_SZ + OFF_AL, Alo, lda2, kt_b);
        ldg_B_nn(sb + ST_SZ + OFF_BH, Bhi, ldb2, kt_b); ldg_B_nn(sb + ST_SZ + OFF_BL, Blo, ldb2, kt_b);
        CP_COMMIT();
    }
    int stage = 0;
    while (true) {
        if (has_b) CP_WAIT1(); else CP_WAIT0();
        __syncthreads();
        compute_chunk<true>(sb + stage * ST_SZ, C);
        __syncthreads();
        if (!has_b) break;
        int kt_c = kt_b + 32;
        while (kt_c < SS && kt_c + 32 <= q0 && !p32[kt_c >> 5]) kt_c += 32;
        bool has_c = (kt_c < SS);
        if (has_c) {
            uint32_t d = sb + stage * ST_SZ;
            ldg_A(d + OFF_AH, Ahi, lda2, kt_c); ldg_A(d + OFF_AL, Alo, lda2, kt_c);
            ldg_B_nn(d + OFF_BH, Bhi, ldb2, kt_c); ldg_B_nn(d + OFF_BL, Blo, ldb2, kt_c);
            CP_COMMIT();
        }
        stage ^= 1;
        kt_b = kt_c;
        has_b = has_c;
    }

    const int lane = threadIdx.x & 31, wid = threadIdx.x >> 5;
    const int wm = wid >> 2, wn = wid & 3;
    const float* norm2 = g_norm2 + (size_t)h * BB * SS;
#pragma unroll
    for (int mt = 0; mt < 4; mt++) {
        const int r0 = wm * 64 + mt * 16 + (lane >> 2);
        const int qA = q0 + r0, qB = qA + 8;
        const float invA = 1.f / fmaxf(sqrtf(norm2[b * SS + qA]), 1e-5f);
        const float invB = 1.f / fmaxf(sqrtf(norm2[b * SS + qB]), 1e-5f);
#pragma unroll
        for (int nt = 0; nt < 8; nt++) {
            const int col = n0 + wn * 64 + nt * 8 + (lane & 3) * 2;
            float v0 = C[mt][nt][0] * invA, v1 = C[mt][nt][1] * invA;
            float v2 = C[mt][nt][2] * invB, v3 = C[mt][nt][3] * invB;
            const size_t oA = ((size_t)b * SS + qA) * DD + col;
            const size_t oB = ((size_t)b * SS + qB) * DD + col;
            *(uint32_t*)(g_x_hi + oA) = packsplit_hi(v0, v1);
            *(uint32_t*)(g_x_lo + oA) = packsplit_lo(v0, v1);
            *(uint32_t*)(g_x_hi + oB) = packsplit_hi(v2, v3);
            *(uint32_t*)(g_x_lo + oB) = packsplit_lo(v2, v3);
            float2* opA = (float2*)(out + oA);
            float2* opB = (float2*)(out + oB);
            float2 a = *opA; a.x += v0; a.y += v1; *opA = a;
            float2 c = *opB; c.x += v2; c.y += v3; *opB = c;
        }
    }
}

// ---------------------------------------------------------------------------
// setup kernels (2 launches, vectorized)
// ---------------------------------------------------------------------------
__global__ void k_setup1(const float4* __restrict__ x_in, const float4* __restrict__ W) {
    const size_t NX4 = ((size_t)BB * SS * DD) / 4;
    size_t i = (size_t)blockIdx.x * NTHR + threadIdx.x;
    float4 v;
    uint32_t* dh;
    uint32_t* dl;
    if (i < NX4) {
        v = x_in[i];
        dh = (uint32_t*)(g_x_hi + i * 4);
        dl = (uint32_t*)(g_x_lo + i * 4);
    } else {
        size_t k = i - NX4;
        v = W[k];
        dh = (uint32_t*)(g_w_hi + k * 4);
        dl = (uint32_t*)(g_w_lo + k * 4);
    }
    dh[0] = packsplit_hi(v.x, v.y);
    dh[1] = packsplit_hi(v.z, v.w);
    dl[0] = packsplit_lo(v.x, v.y);
    dl[1] = packsplit_lo(v.z, v.w);
}
__global__ void k_setup2(const int* __restrict__ et, float4* __restrict__ out4) {
    size_t i = (size_t)blockIdx.x * NTHR + threadIdx.x;
    out4[i] = make_float4(0.f, 0.f, 0.f, 0.f);
    if (i < (HH * BB * SS) / 4)
        ((float4*)g_norm2)[i] = make_float4(0.f, 0.f, 0.f, 0.f);
    if (i < BB * (SS / 32)) {                           // 512 pad32 flags
        int b = (int)(i >> 5), cc = (int)(i & 31);
        int any = 0;
        const int4* p = (const int4*)(et + b * SS + cc * 32);
#pragma unroll
        for (int t = 0; t < 8; t++) {
            int4 e = p[t];
            any |= (e.x == 0) | (e.y == 0) | (e.z == 0) | (e.w == 0);
        }
        g_pad32[i] = any;
    }
    if (i >= 1024 && i < 1024 + BB * (SS / 256)) {      // 64 pad256 flags
        int idx = (int)(i - 1024);
        int b = idx >> 2, kb = idx & 3;
        int any = 0;
        const int4* p = (const int4*)(et + b * SS + kb * 256);
#pragma unroll
        for (int t = 0; t < 64; t++) {
            int4 e = p[t];
            any |= (e.x == 0) | (e.y == 0) | (e.z == 0) | (e.w == 0);
        }
        g_pad256[idx] = any;
    }
}

// ---------------------------------------------------------------------------
extern "C" void kernel_launch(void* const* d_in, const int* in_sizes, int n_in,
                              void* d_out, int out_size) {
    const float* x_in = (const float*)d_in[0];   // [B,S,D] fp32
    const int* et = (const int*)d_in[2];         // [B,S] int32
    const float* W = (const float*)d_in[3];      // [H,D,D] fp32
    const float* bias = (const float*)d_in[4];   // [H,D] fp32
    float* out = (float*)d_out;

    static int configured = 0;
    if (!configured) {
        cudaFuncSetAttribute(k_qkv, cudaFuncAttributeMaxDynamicSharedMemorySize, SMEM_SZ);
        cudaFuncSetAttribute(k_av,  cudaFuncAttributeMaxDynamicSharedMemorySize, SMEM_SZ);
        configured = 1;
    }

    k_setup1<<<9216, NTHR>>>((const float4*)x_in, (const float4*)W);
    k_setup2<<<8192, NTHR>>>(et, (float4*)out);

    const dim3 grid_av(2, 8, BB);
    for (int h = 0; h < HH; h++) {
        k_qkv<<<768, NTHR, SMEM_SZ>>>(h, et, bias + (size_t)h * DD);
        k_av<<<grid_av, NTHR, SMEM_SZ>>>(h, out);
    }
}

// round 15
// speedup vs baseline: 1.3514x; 1.3514x over previous
#include <cuda_runtime.h>
#include <cuda_bf16.h>
#include <math.h>
#include <stdint.h>

// Problem constants
#define BB 16
#define SS 1024
#define DD 512
#define HH 4
#define NTHR 256

// smem staging: per stage 4 tiles (A hi/lo 128x(32+8)bf16, B hi/lo)
#define ST_SZ  40960
#define OFF_AH 0
#define OFF_AL 10240
#define OFF_BH 20480
#define OFF_BL 30720
#define SMEM_SZ (2 * ST_SZ)

#define STRA 80    // bytes per A/B-NT smem row (40 bf16)
#define STRB 272   // bytes per B-NN smem row (136 bf16)

// ---------------- device scratch ----------------
__device__ __align__(16) __nv_bfloat16 g_x_hi[(size_t)BB*SS*DD];
__device__ __align__(16) __nv_bfloat16 g_x_lo[(size_t)BB*SS*DD];
__device__ __align__(16) __nv_bfloat16 g_v_hi[(size_t)BB*SS*DD];
__device__ __align__(16) __nv_bfloat16 g_v_lo[(size_t)BB*SS*DD];
__device__ __align__(16) __nv_bfloat16 g_attn_hi[(size_t)BB*SS*SS];
__device__ __align__(16) __nv_bfloat16 g_attn_lo[(size_t)BB*SS*SS];
__device__ __align__(16) __nv_bfloat16 g_w_hi[(size_t)HH*DD*DD];
__device__ __align__(16) __nv_bfloat16 g_w_lo[(size_t)HH*DD*DD];
__device__ __align__(16) float g_norm2[HH * BB * SS];
__device__ int g_pad32[BB*(SS/32)];
__device__ int g_padblk[BB*(SS/128)];

// ---------------- PTX helpers (sm_80-level only; harness targets plain sm_103) ----
#define CPA16(s, g) asm volatile("cp.async.cg.shared.global [%0], [%1], 16;" :: "r"(s), "l"(g))
#define CP_COMMIT() asm volatile("cp.async.commit_group;" ::: "memory")
#define CP_WAIT0()  asm volatile("cp.async.wait_group 0;" ::: "memory")

#define LDSMX4(r0, r1, r2, r3, a)                                              \
    asm volatile("ldmatrix.sync.aligned.m8n8.x4.shared.b16 {%0,%1,%2,%3}, [%4];" \
                 : "=r"(r0), "=r"(r1), "=r"(r2), "=r"(r3) : "r"(a))
#define LDSMX4T(r0, r1, r2, r3, a)                                             \
    asm volatile("ldmatrix.sync.aligned.m8n8.x4.trans.shared.b16 {%0,%1,%2,%3}, [%4];" \
                 : "=r"(r0), "=r"(r1), "=r"(r2), "=r"(r3) : "r"(a))

#define MMA16816(c, a, b0v, b1v)                                               \
    asm volatile(                                                              \
        "mma.sync.aligned.m16n8k16.row.col.f32.bf16.bf16.f32 "                 \
        "{%0,%1,%2,%3}, {%4,%5,%6,%7}, {%8,%9}, {%0,%1,%2,%3};"                \
        : "+f"((c)[0]), "+f"((c)[1]), "+f"((c)[2]), "+f"((c)[3])               \
        : "r"((a)[0]), "r"((a)[1]), "r"((a)[2]), "r"((a)[3]), "r"(b0v), "r"(b1v))

// ---------------- tile loaders (256 threads) ----------------
__device__ __forceinline__ void ldg_128x32(uint32_t dst, const char* src, size_t ld2, int kt) {
#pragma unroll
    for (int p = 0; p < 2; p++) {
        int i = threadIdx.x + p * NTHR;
        int row = i >> 2, seg = i & 3;
        CPA16(dst + row * STRA + seg * 16,
              src + (size_t)row * ld2 + (size_t)kt * 2 + seg * 16);
    }
}
__device__ __forceinline__ void ldg_32x128(uint32_t dst, const char* src, size_t ld2, int kt) {
#pragma unroll
    for (int p = 0; p < 2; p++) {
        int i = threadIdx.x + p * NTHR;
        int row = i >> 4, seg = i & 15;
        CPA16(dst + row * STRB + seg * 16,
              src + (size_t)(kt + row) * ld2 + seg * 16);
    }
}

// ---------------- warp MMA compute on one staged 128x128x32 chunk ------------
// Warp layout: 8 warps = 2(m) x 4(n); warp tile 64x32; mma m16n8k16.
template <bool BT>
__device__ __forceinline__ void compute_chunk(uint32_t sbase, float (&C)[4][4][4]) {
    const int lane = threadIdx.x & 31;
    const int wid = threadIdx.x >> 5;
    const int wm = wid >> 2, wn = wid & 3;
#pragma unroll
    for (int ks = 0; ks < 2; ks++) {
        uint32_t ah[4][4], al[4][4];
#pragma unroll
        for (int mt = 0; mt < 4; mt++) {
            uint32_t ra = sbase + OFF_AH +
                (uint32_t)((wm * 64 + mt * 16 + (lane & 15)) * STRA + ks * 32 + (lane >> 4) * 16);
            LDSMX4(ah[mt][0], ah[mt][1], ah[mt][2], ah[mt][3], ra);
            ra += (OFF_AL - OFF_AH);
            LDSMX4(al[mt][0], al[mt][1], al[mt][2], al[mt][3], ra);
        }
        uint32_t bh[2][4], bl[2][4];
#pragma unroll
        for (int ntp = 0; ntp < 2; ntp++) {
            if (!BT) {
                uint32_t rb = sbase + OFF_BH +
                    (uint32_t)((wn * 32 + ntp * 16 + (lane >> 4) * 8 + (lane & 7)) * STRA +
                               ks * 32 + ((lane >> 3) & 1) * 16);
                LDSMX4(bh[ntp][0], bh[ntp][1], bh[ntp][2], bh[ntp][3], rb);
                rb += (OFF_BL - OFF_BH);
                LDSMX4(bl[ntp][0], bl[ntp][1], bl[ntp][2], bl[ntp][3], rb);
            } else {
                uint32_t rb = sbase + OFF_BH +
                    (uint32_t)((ks * 16 + ((lane >> 3) & 1) * 8 + (lane & 7)) * STRB +
                               (wn * 32 + ntp * 16) * 2 + (lane >> 4) * 16);
                LDSMX4T(bh[ntp][0], bh[ntp][1], bh[ntp][2], bh[ntp][3], rb);
                rb += (OFF_BL - OFF_BH);
                LDSMX4T(bl[ntp][0], bl[ntp][1], bl[ntp][2], bl[ntp][3], rb);
            }
        }
#pragma unroll
        for (int mt = 0; mt < 4; mt++)
#pragma unroll
            for (int nt = 0; nt < 4; nt++) {
                const int p = nt >> 1, j = (nt & 1) * 2;
                MMA16816(C[mt][nt], ah[mt], bh[p][j], bh[p][j + 1]);
                MMA16816(C[mt][nt], ah[mt], bl[p][j], bl[p][j + 1]);
                MMA16816(C[mt][nt], al[mt], bh[p][j], bh[p][j + 1]);
            }
    }
}

__device__ __forceinline__ void zeroC(float (&C)[4][4][4]) {
#pragma unroll
    for (int a = 0; a < 4; a++)
#pragma unroll
        for (int b = 0; b < 4; b++)
#pragma unroll
            for (int c = 0; c < 4; c++) C[a][b][c] = 0.f;
}
__device__ __forceinline__ uint32_t packsplit_hi(float v0, float v1) {
    __nv_bfloat162 h = __floats2bfloat162_rn(v0, v1);
    return *(uint32_t*)&h;
}
__device__ __forceinline__ uint32_t packsplit_lo(float v0, float v1) {
    float r0 = v0 - __bfloat162float(__float2bfloat16(v0));
    float r1 = v1 - __bfloat162float(__float2bfloat16(v1));
    __nv_bfloat162 l = __floats2bfloat162_rn(r0, r1);
    return *(uint32_t*)&l;
}

// dense-K 16-chunk mainloop, SINGLE sync per chunk:
//   wait(ci done) -> sync -> issue ci+1 into other stage -> compute ci
__device__ __forceinline__ void mainloop_dense(uint32_t sb,
                                               const char* Ahi, const char* Alo,
                                               const char* Bhi, const char* Blo,
                                               size_t ld2, float (&C)[4][4][4]) {
    ldg_128x32(sb + OFF_AH, Ahi, ld2, 0); ldg_128x32(sb + OFF_AL, Alo, ld2, 0);
    ldg_128x32(sb + OFF_BH, Bhi, ld2, 0); ldg_128x32(sb + OFF_BL, Blo, ld2, 0);
    CP_COMMIT();
    int stage = 0;
    for (int ci = 0; ci < 16; ci++) {
        CP_WAIT0();
        __syncthreads();
        if (ci + 1 < 16) {
            uint32_t d = sb + (stage ^ 1) * ST_SZ;
            int kt = (ci + 1) * 32;
            ldg_128x32(d + OFF_AH, Ahi, ld2, kt); ldg_128x32(d + OFF_AL, Alo, ld2, kt);
            ldg_128x32(d + OFF_BH, Bhi, ld2, kt); ldg_128x32(d + OFF_BL, Blo, ld2, kt);
            CP_COMMIT();
        }
        compute_chunk<false>(sb + stage * ST_SZ, C);
        stage ^= 1;
    }
}

// ---------------------------------------------------------------------------
// Fused K1+K3: blocks [0,1024) do qk tiles, blocks [1024,1536) do v tiles.
// ---------------------------------------------------------------------------
__global__ __launch_bounds__(NTHR, 2) void k_qkv(int h, const int* __restrict__ et,
                                                 const float* __restrict__ bias) {
    extern __shared__ char smem[];
    const uint32_t sb = (uint32_t)__cvta_generic_to_shared(smem);
    const int flat = blockIdx.x;
    const int lane = threadIdx.x & 31, wid = threadIdx.x >> 5;
    const int wm = wid >> 2, wn = wid & 3;
    const size_t ld2 = (size_t)DD * 2;

    if (flat < 1024) {
        // ---------------- qk path ----------------
        const int b = flat >> 6, qi = (flat >> 3) & 7, ki = flat & 7;
        const int q0 = qi * 128, k0 = ki * 128;
        const bool below = (k0 < q0);
        if (below && !g_padblk[b * 8 + ki]) return;
        const bool above = (k0 > q0);

        const char* Ahi = (const char*)g_x_hi + ((size_t)b * SS + q0) * DD * 2;
        const char* Alo = (const char*)g_x_lo + ((size_t)b * SS + q0) * DD * 2;
        const char* Bhi = (const char*)g_x_hi + ((size_t)b * SS + k0) * DD * 2;
        const char* Blo = (const char*)g_x_lo + ((size_t)b * SS + k0) * DD * 2;

        float C[4][4][4];
        zeroC(C);
        mainloop_dense(sb, Ahi, Alo, Bhi, Blo, ld2, C);

        const float invtemp = 0.04419417382415922f;  // 1/sqrt(512)
        float* norm2 = g_norm2 + (size_t)h * BB * SS;

        int kg[4]; bool pad0[4], pad1[4];
#pragma unroll
        for (int nt = 0; nt < 4; nt++) {
            kg[nt] = k0 + wn * 32 + nt * 8 + (lane & 3) * 2;
            pad0[nt] = (__ldg(et + b * SS + kg[nt]) == 0);
            pad1[nt] = (__ldg(et + b * SS + kg[nt] + 1) == 0);
        }
#pragma unroll
        for (int mt = 0; mt < 4; mt++) {
            const int r0 = wm * 64 + mt * 16 + (lane >> 2);
            const int qA = q0 + r0, qB = q0 + r0 + 8;
            float sqA = 0.f, sqB = 0.f;
#pragma unroll
            for (int nt = 0; nt < 4; nt++) {
                float v0 = C[mt][nt][0] * invtemp, v1 = C[mt][nt][1] * invtemp;
                float v2 = C[mt][nt][2] * invtemp, v3 = C[mt][nt][3] * invtemp;
                bool kA0 = above || (kg[nt] > qA) || pad0[nt];
                bool kA1 = above || (kg[nt] + 1 > qA) || pad1[nt];
                bool kB0 = above || (kg[nt] > qB) || pad0[nt];
                bool kB1 = above || (kg[nt] + 1 > qB) || pad1[nt];
                v0 = kA0 ? v0 : 0.f; v1 = kA1 ? v1 : 0.f;
                v2 = kB0 ? v2 : 0.f; v3 = kB1 ? v3 : 0.f;
                sqA = fmaf(v0, v0, fmaf(v1, v1, sqA));
                sqB = fmaf(v2, v2, fmaf(v3, v3, sqB));
                const size_t oA = ((size_t)b * SS + qA) * SS + kg[nt];
                const size_t oB = ((size_t)b * SS + qB) * SS + kg[nt];
                *(uint32_t*)(g_attn_hi + oA) = packsplit_hi(v0, v1);
                *(uint32_t*)(g_attn_lo + oA) = packsplit_lo(v0, v1);
                *(uint32_t*)(g_attn_hi + oB) = packsplit_hi(v2, v3);
                *(uint32_t*)(g_attn_lo + oB) = packsplit_lo(v2, v3);
            }
            sqA += __shfl_xor_sync(0xffffffffu, sqA, 1);
            sqA += __shfl_xor_sync(0xffffffffu, sqA, 2);
            sqB += __shfl_xor_sync(0xffffffffu, sqB, 1);
            sqB += __shfl_xor_sync(0xffffffffu, sqB, 2);
            if ((lane & 3) == 0) {
                atomicAdd(&norm2[b * SS + qA], sqA);
                atomicAdd(&norm2[b * SS + qB], sqB);
            }
        }
    } else {
        // ---------------- v path ----------------
        const int f = flat - 1024;           // 0..511
        const int m0 = (f >> 2) * 128, n0 = (f & 3) * 128;

        const char* Ahi = (const char*)g_x_hi + (size_t)m0 * DD * 2;
        const char* Alo = (const char*)g_x_lo + (size_t)m0 * DD * 2;
        const char* Bhi = (const char*)g_w_hi + ((size_t)h * DD * DD + (size_t)n0 * DD) * 2;
        const char* Blo = (const char*)g_w_lo + ((size_t)h * DD * DD + (size_t)n0 * DD) * 2;

        float C[4][4][4];
        zeroC(C);
        mainloop_dense(sb, Ahi, Alo, Bhi, Blo, ld2, C);

        float b0[4], b1[4]; int col[4];
#pragma unroll
        for (int nt = 0; nt < 4; nt++) {
            col[nt] = n0 + wn * 32 + nt * 8 + (lane & 3) * 2;
            b0[nt] = __ldg(bias + col[nt]);
            b1[nt] = __ldg(bias + col[nt] + 1);
        }
#pragma unroll
        for (int mt = 0; mt < 4; mt++) {
            const int r0 = wm * 64 + mt * 16 + (lane >> 2);
            const size_t mA = (size_t)(m0 + r0), mB = mA + 8;
#pragma unroll
            for (int nt = 0; nt < 4; nt++) {
                float v0 = C[mt][nt][0] + b0[nt], v1 = C[mt][nt][1] + b1[nt];
                float v2 = C[mt][nt][2] + b0[nt], v3 = C[mt][nt][3] + b1[nt];
                v0 = (v0 > 0.f) ? v0 : expm1f(v0);
                v1 = (v1 > 0.f) ? v1 : expm1f(v1);
                v2 = (v2 > 0.f) ? v2 : expm1f(v2);
                v3 = (v3 > 0.f) ? v3 : expm1f(v3);
                const size_t oA = mA * DD + col[nt], oB = mB * DD + col[nt];
                *(uint32_t*)(g_v_hi + oA) = packsplit_hi(v0, v1);
                *(uint32_t*)(g_v_lo + oA) = packsplit_lo(v0, v1);
                *(uint32_t*)(g_v_hi + oB) = packsplit_hi(v2, v3);
                *(uint32_t*)(g_v_lo + oB) = packsplit_lo(v2, v3);
            }
        }
    }
}

// ---------------------------------------------------------------------------
// K4: xnew = invnorm * (attn · v); single-sync pipelined with chunk skipping.
// ---------------------------------------------------------------------------
__global__ __launch_bounds__(NTHR, 2) void k_av(int h, float* __restrict__ out) {
    const int b = blockIdx.z, q0 = blockIdx.y * 128, n0 = blockIdx.x * 128;
    extern __shared__ char smem[];
    const uint32_t sb = (uint32_t)__cvta_generic_to_shared(smem);

    const char* Ahi = (const char*)g_attn_hi + ((size_t)b * SS + q0) * SS * 2;
    const char* Alo = (const char*)g_attn_lo + ((size_t)b * SS + q0) * SS * 2;
    const char* Bhi = (const char*)g_v_hi + ((size_t)b * SS * DD + n0) * 2;
    const char* Blo = (const char*)g_v_lo + ((size_t)b * SS * DD + n0) * 2;
    const size_t lda2 = (size_t)SS * 2, ldb2 = (size_t)DD * 2;
    const int* p32 = g_pad32 + b * (SS / 32);

    float C[4][4][4];
    zeroC(C);

    // first active chunk (always exists: diagonal band is kept)
    int kt_cur = 0;
    while (kt_cur + 32 <= q0 && !p32[kt_cur >> 5]) kt_cur += 32;

    ldg_128x32(sb + OFF_AH, Ahi, lda2, kt_cur); ldg_128x32(sb + OFF_AL, Alo, lda2, kt_cur);
    ldg_32x128(sb + OFF_BH, Bhi, ldb2, kt_cur); ldg_32x128(sb + OFF_BL, Blo, ldb2, kt_cur);
    CP_COMMIT();

    int stage = 0;
    while (kt_cur < SS) {
        int kt_next = kt_cur + 32;
        while (kt_next < SS && kt_next + 32 <= q0 && !p32[kt_next >> 5]) kt_next += 32;

        CP_WAIT0();
        __syncthreads();
        if (kt_next < SS) {
            uint32_t d = sb + (stage ^ 1) * ST_SZ;
            ldg_128x32(d + OFF_AH, Ahi, lda2, kt_next); ldg_128x32(d + OFF_AL, Alo, lda2, kt_next);
            ldg_32x128(d + OFF_BH, Bhi, ldb2, kt_next); ldg_32x128(d + OFF_BL, Blo, ldb2, kt_next);
            CP_COMMIT();
        }
        compute_chunk<true>(sb + stage * ST_SZ, C);
        stage ^= 1;
        kt_cur = kt_next;
    }

    const int lane = threadIdx.x & 31, wid = threadIdx.x >> 5;
    const int wm = wid >> 2, wn = wid & 3;
    const float* norm2 = g_norm2 + (size_t)h * BB * SS;
#pragma unroll
    for (int mt = 0; mt < 4; mt++) {
        const int r0 = wm * 64 + mt * 16 + (lane >> 2);
        const int qA = q0 + r0, qB = qA + 8;
        const float invA = 1.f / fmaxf(sqrtf(norm2[b * SS + qA]), 1e-5f);
        const float invB = 1.f / fmaxf(sqrtf(norm2[b * SS + qB]), 1e-5f);
#pragma unroll
        for (int nt = 0; nt < 4; nt++) {
            const int col = n0 + wn * 32 + nt * 8 + (lane & 3) * 2;
            float v0 = C[mt][nt][0] * invA, v1 = C[mt][nt][1] * invA;
            float v2 = C[mt][nt][2] * invB, v3 = C[mt][nt][3] * invB;
            const size_t oA = ((size_t)b * SS + qA) * DD + col;
            const size_t oB = ((size_t)b * SS + qB) * DD + col;
            *(uint32_t*)(g_x_hi + oA) = packsplit_hi(v0, v1);
            *(uint32_t*)(g_x_lo + oA) = packsplit_lo(v0, v1);
            *(uint32_t*)(g_x_hi + oB) = packsplit_hi(v2, v3);
            *(uint32_t*)(g_x_lo + oB) = packsplit_lo(v2, v3);
            float2* opA = (float2*)(out + oA);
            float2* opB = (float2*)(out + oB);
            float2 a = *opA; a.x += v0; a.y += v1; *opA = a;
            float2 c = *opB; c.x += v2; c.y += v3; *opB = c;
        }
    }
}

// ---------------------------------------------------------------------------
// setup kernels (2 launches, vectorized: 4 elems/thread)
// ---------------------------------------------------------------------------
__global__ void k_setup1(const float4* __restrict__ x_in, const float4* __restrict__ W) {
    const size_t NX4 = ((size_t)BB * SS * DD) / 4;      // 2,097,152
    size_t i = (size_t)blockIdx.x * NTHR + threadIdx.x; // < 2,359,296
    float4 v;
    uint32_t* dh;
    uint32_t* dl;
    if (i < NX4) {
        v = x_in[i];
        dh = (uint32_t*)(g_x_hi + i * 4);
        dl = (uint32_t*)(g_x_lo + i * 4);
    } else {
        size_t k = i - NX4;
        v = W[k];
        dh = (uint32_t*)(g_w_hi + k * 4);
        dl = (uint32_t*)(g_w_lo + k * 4);
    }
    dh[0] = packsplit_hi(v.x, v.y);
    dh[1] = packsplit_hi(v.z, v.w);
    dl[0] = packsplit_lo(v.x, v.y);
    dl[1] = packsplit_lo(v.z, v.w);
}
__global__ void k_setup2(const int* __restrict__ et, float4* __restrict__ out4) {
    size_t i = (size_t)blockIdx.x * NTHR + threadIdx.x;
    out4[i] = make_float4(0.f, 0.f, 0.f, 0.f);          // 2M float4 = 8.4M floats
    if (i < (HH * BB * SS) / 4)
        ((float4*)g_norm2)[i] = make_float4(0.f, 0.f, 0.f, 0.f);
    if (i < BB * (SS / 32)) {                           // 512 pad32 flags
        int b = (int)(i >> 5), cc = (int)(i & 31);
        int any = 0;
        const int4* p = (const int4*)(et + b * SS + cc * 32);
#pragma unroll
        for (int t = 0; t < 8; t++) {
            int4 e = p[t];
            any |= (e.x == 0) | (e.y == 0) | (e.z == 0) | (e.w == 0);
        }
        g_pad32[i] = any;
    }
    if (i >= 1024 && i < 1024 + BB * (SS / 128)) {      // 128 padblk flags (from et)
        int idx = (int)(i - 1024);
        int b = idx >> 3, kb = idx & 7;
        int any = 0;
        const int4* p = (const int4*)(et + b * SS + kb * 128);
#pragma unroll
        for (int t = 0; t < 32; t++) {
            int4 e = p[t];
            any |= (e.x == 0) | (e.y == 0) | (e.z == 0) | (e.w == 0);
        }
        g_padblk[idx] = any;
    }
}

// ---------------------------------------------------------------------------
extern "C" void kernel_launch(void* const* d_in, const int* in_sizes, int n_in,
                              void* d_out, int out_size) {
    const float* x_in = (const float*)d_in[0];   // [B,S,D] fp32
    const int* et = (const int*)d_in[2];         // [B,S] int32
    const float* W = (const float*)d_in[3];      // [H,D,D] fp32
    const float* bias = (const float*)d_in[4];   // [H,D] fp32
    float* out = (float*)d_out;

    static int configured = 0;
    if (!configured) {
        cudaFuncSetAttribute(k_qkv, cudaFuncAttributeMaxDynamicSharedMemorySize, SMEM_SZ);
        cudaFuncSetAttribute(k_av,  cudaFuncAttributeMaxDynamicSharedMemorySize, SMEM_SZ);
        configured = 1;
    }

    k_setup1<<<9216, NTHR>>>((const float4*)x_in, (const float4*)W);
    k_setup2<<<8192, NTHR>>>(et, (float4*)out);

    const dim3 grid_av(4, 8, BB);
    for (int h = 0; h < HH; h++) {
        k_qkv<<<1536, NTHR, SMEM_SZ>>>(h, et, bias + (size_t)h * DD);
        k_av<<<grid_av, NTHR, SMEM_SZ>>>(h, out);
    }
}

// round 16
// speedup vs baseline: 1.4485x; 1.0719x over previous
#include <cuda_runtime.h>
#include <cuda_bf16.h>
#include <math.h>
#include <stdint.h>

// Problem constants
#define BB 16
#define SS 1024
#define DD 512
#define HH 4
#define NTHR 256

// smem staging: per stage 4 tiles (A hi/lo 128x(32+8)bf16, B hi/lo)
#define ST_SZ  40960
#define OFF_AH 0
#define OFF_AL 10240
#define OFF_BH 20480
#define OFF_BL 30720
// mbarriers after the two stages
#define MB_READY0 (2 * ST_SZ)
#define MB_READY1 (MB_READY0 + 8)
#define MB_FREE0  (MB_READY0 + 16)
#define MB_FREE1  (MB_READY0 + 24)
#define SMEM_TOT  (MB_READY0 + 32)

#define STRA 80    // bytes per A/B-NT smem row (40 bf16)
#define STRB 272   // bytes per B-NN smem row (136 bf16)

// ---------------- device scratch ----------------
__device__ __align__(16) __nv_bfloat16 g_x_hi[(size_t)BB*SS*DD];
__device__ __align__(16) __nv_bfloat16 g_x_lo[(size_t)BB*SS*DD];
__device__ __align__(16) __nv_bfloat16 g_v_hi[(size_t)BB*SS*DD];
__device__ __align__(16) __nv_bfloat16 g_v_lo[(size_t)BB*SS*DD];
__device__ __align__(16) __nv_bfloat16 g_attn_hi[(size_t)BB*SS*SS];
__device__ __align__(16) __nv_bfloat16 g_attn_lo[(size_t)BB*SS*SS];
__device__ __align__(16) __nv_bfloat16 g_w_hi[(size_t)HH*DD*DD];
__device__ __align__(16) __nv_bfloat16 g_w_lo[(size_t)HH*DD*DD];
__device__ __align__(16) float g_norm2[HH * BB * SS];
__device__ int g_pad32[BB*(SS/32)];
__device__ int g_padblk[BB*(SS/128)];

// ---------------- PTX helpers (sm_80/90 base ISA; harness targets plain sm_103) ----
#define CPA16(s, g) asm volatile("cp.async.cg.shared.global [%0], [%1], 16;" :: "r"(s), "l"(g))
#define CPA_MBAR(a) asm volatile("cp.async.mbarrier.arrive.noinc.shared.b64 [%0];" :: "r"(a) : "memory")
#define MBAR_INIT(a, n) asm volatile("mbarrier.init.shared.b64 [%0], %1;" :: "r"(a), "r"(n) : "memory")
// arrive with a dummy data dependency: orders the arrive after the producing ldsm
#define MBAR_ARRIVE_DEP(a, dep)                                                \
    asm volatile("{\n\t.reg .b64 t;\n\tmbarrier.arrive.shared.b64 t, [%0];\n\t}" \
                 :: "r"(a), "r"(dep) : "memory")
#define MBAR_WAIT(addr, ph) do {                                               \
    uint32_t _m = (addr), _p = (uint32_t)(ph), _d;                             \
    asm volatile("{\n\t.reg .pred p;\n\t"                                      \
        "mbarrier.try_wait.parity.acquire.cta.shared::cta.b64 p, [%1], %2;\n\t" \
        "selp.b32 %0, 1, 0, p;\n\t}" : "=r"(_d) : "r"(_m), "r"(_p) : "memory"); \
    if (!_d) {                                                                 \
        asm volatile("{\n\t.reg .pred P1;\n\tWL_%=:\n\t"                       \
            "mbarrier.try_wait.parity.acquire.cta.shared::cta.b64 P1, [%0], %1, 0x989680;\n\t" \
            "@P1 bra.uni WD_%=;\n\tbra.uni WL_%=;\n\tWD_%=:\n\t}"              \
            :: "r"(_m), "r"(_p) : "memory");                                   \
    }                                                                          \
} while (0)

#define LDSMX4(r0, r1, r2, r3, a)                                              \
    asm volatile("ldmatrix.sync.aligned.m8n8.x4.shared.b16 {%0,%1,%2,%3}, [%4];" \
                 : "=r"(r0), "=r"(r1), "=r"(r2), "=r"(r3) : "r"(a))
#define LDSMX4T(r0, r1, r2, r3, a)                                             \
    asm volatile("ldmatrix.sync.aligned.m8n8.x4.trans.shared.b16 {%0,%1,%2,%3}, [%4];" \
                 : "=r"(r0), "=r"(r1), "=r"(r2), "=r"(r3) : "r"(a))

#define MMA16816(c, a, b0v, b1v)                                               \
    asm volatile(                                                              \
        "mma.sync.aligned.m16n8k16.row.col.f32.bf16.bf16.f32 "                 \
        "{%0,%1,%2,%3}, {%4,%5,%6,%7}, {%8,%9}, {%0,%1,%2,%3};"                \
        : "+f"((c)[0]), "+f"((c)[1]), "+f"((c)[2]), "+f"((c)[3])               \
        : "r"((a)[0]), "r"((a)[1]), "r"((a)[2]), "r"((a)[3]), "r"(b0v), "r"(b1v))

// ---------------- tile loaders (256 threads) ----------------
__device__ __forceinline__ void ldg_128x32(uint32_t dst, const char* src, size_t ld2, int kt) {
#pragma unroll
    for (int p = 0; p < 2; p++) {
        int i = threadIdx.x + p * NTHR;
        int row = i >> 2, seg = i & 3;
        CPA16(dst + row * STRA + seg * 16,
              src + (size_t)row * ld2 + (size_t)kt * 2 + seg * 16);
    }
}
__device__ __forceinline__ void ldg_32x128(uint32_t dst, const char* src, size_t ld2, int kt) {
#pragma unroll
    for (int p = 0; p < 2; p++) {
        int i = threadIdx.x + p * NTHR;
        int row = i >> 4, seg = i & 15;
        CPA16(dst + row * STRB + seg * 16,
              src + (size_t)(kt + row) * ld2 + seg * 16);
    }
}

// ---------------- ldsm / mma halves (one ks of a 128x128x32 chunk) ----------
template <bool BT>
__device__ __forceinline__ void ldsm_half(uint32_t sbase, int ks,
                                          uint32_t (&ah)[4][4], uint32_t (&al)[4][4],
                                          uint32_t (&bh)[2][4], uint32_t (&bl)[2][4]) {
    const int lane = threadIdx.x & 31;
    const int wid = threadIdx.x >> 5;
    const int wm = wid >> 2, wn = wid & 3;
#pragma unroll
    for (int mt = 0; mt < 4; mt++) {
        uint32_t ra = sbase + OFF_AH +
            (uint32_t)((wm * 64 + mt * 16 + (lane & 15)) * STRA + ks * 32 + (lane >> 4) * 16);
        LDSMX4(ah[mt][0], ah[mt][1], ah[mt][2], ah[mt][3], ra);
        ra += (OFF_AL - OFF_AH);
        LDSMX4(al[mt][0], al[mt][1], al[mt][2], al[mt][3], ra);
    }
#pragma unroll
    for (int ntp = 0; ntp < 2; ntp++) {
        if (!BT) {
            uint32_t rb = sbase + OFF_BH +
                (uint32_t)((wn * 32 + ntp * 16 + (lane >> 4) * 8 + (lane & 7)) * STRA +
                           ks * 32 + ((lane >> 3) & 1) * 16);
            LDSMX4(bh[ntp][0], bh[ntp][1], bh[ntp][2], bh[ntp][3], rb);
            rb += (OFF_BL - OFF_BH);
            LDSMX4(bl[ntp][0], bl[ntp][1], bl[ntp][2], bl[ntp][3], rb);
        } else {
            uint32_t rb = sbase + OFF_BH +
                (uint32_t)((ks * 16 + ((lane >> 3) & 1) * 8 + (lane & 7)) * STRB +
                           (wn * 32 + ntp * 16) * 2 + (lane >> 4) * 16);
            LDSMX4T(bh[ntp][0], bh[ntp][1], bh[ntp][2], bh[ntp][3], rb);
            rb += (OFF_BL - OFF_BH);
            LDSMX4T(bl[ntp][0], bl[ntp][1], bl[ntp][2], bl[ntp][3], rb);
        }
    }
}
__device__ __forceinline__ void mma_half(const uint32_t (&ah)[4][4], const uint32_t (&al)[4][4],
                                         const uint32_t (&bh)[2][4], const uint32_t (&bl)[2][4],
                                         float (&C)[4][4][4]) {
#pragma unroll
    for (int mt = 0; mt < 4; mt++)
#pragma unroll
        for (int nt = 0; nt < 4; nt++) {
            const int p = nt >> 1, j = (nt & 1) * 2;
            MMA16816(C[mt][nt], ah[mt], bh[p][j], bh[p][j + 1]);
            MMA16816(C[mt][nt], ah[mt], bl[p][j], bl[p][j + 1]);
            MMA16816(C[mt][nt], al[mt], bh[p][j], bh[p][j + 1]);
        }
}

__device__ __forceinline__ void zeroC(float (&C)[4][4][4]) {
#pragma unroll
    for (int a = 0; a < 4; a++)
#pragma unroll
        for (int b = 0; b < 4; b++)
#pragma unroll
            for (int c = 0; c < 4; c++) C[a][b][c] = 0.f;
}
__device__ __forceinline__ uint32_t packsplit_hi(float v0, float v1) {
    __nv_bfloat162 h = __floats2bfloat162_rn(v0, v1);
    return *(uint32_t*)&h;
}
__device__ __forceinline__ uint32_t packsplit_lo(float v0, float v1) {
    float r0 = v0 - __bfloat162float(__float2bfloat16(v0));
    float r1 = v1 - __bfloat162float(__float2bfloat16(v1));
    __nv_bfloat162 l = __floats2bfloat162_rn(r0, r1);
    return *(uint32_t*)&l;
}

// init the 4 pipeline mbarriers; one __syncthreads total
__device__ __forceinline__ void pipe_init(uint32_t sb) {
    if (threadIdx.x == 0) {
        MBAR_INIT(sb + MB_READY0, NTHR);
        MBAR_INIT(sb + MB_READY1, NTHR);
        MBAR_INIT(sb + MB_FREE0, 8);
        MBAR_INIT(sb + MB_FREE1, 8);
    }
    __syncthreads();
}

// dense-K 16-chunk mbarrier-pipelined mainloop (both operands NT 128x32 tiles)
__device__ __forceinline__ void mainloop_dense(uint32_t sb,
                                               const char* Ahi, const char* Alo,
                                               const char* Bhi, const char* Blo,
                                               size_t ld2, float (&C)[4][4][4]) {
    const int lane = threadIdx.x & 31;
    // prologue: chunk0 -> stage0, chunk1 -> stage1
    ldg_128x32(sb + OFF_AH, Ahi, ld2, 0); ldg_128x32(sb + OFF_AL, Alo, ld2, 0);
    ldg_128x32(sb + OFF_BH, Bhi, ld2, 0); ldg_128x32(sb + OFF_BL, Blo, ld2, 0);
    CPA_MBAR(sb + MB_READY0);
    ldg_128x32(sb + ST_SZ + OFF_AH, Ahi, ld2, 32); ldg_128x32(sb + ST_SZ + OFF_AL, Alo, ld2, 32);
    ldg_128x32(sb + ST_SZ + OFF_BH, Bhi, ld2, 32); ldg_128x32(sb + ST_SZ + OFF_BL, Blo, ld2, 32);
    CPA_MBAR(sb + MB_READY1);

    uint32_t ah[4][4], al[4][4], bh[2][4], bl[2][4];
    int ph_r0 = 0, ph_r1 = 0, ph_f0 = 0, ph_f1 = 0;
    int s = 0;
    for (int ci = 0; ci < 16; ci++) {
        const uint32_t st = sb + s * ST_SZ;
        const uint32_t rdy = sb + (s ? MB_READY1 : MB_READY0);
        const uint32_t fre = sb + (s ? MB_FREE1 : MB_FREE0);
        MBAR_WAIT(rdy, s ? ph_r1 : ph_r0);
        if (s) ph_r1 ^= 1; else ph_r0 ^= 1;

        ldsm_half<false>(st, 0, ah, al, bh, bl);
        mma_half(ah, al, bh, bl, C);
        ldsm_half<false>(st, 1, ah, al, bh, bl);
        if (lane == 0) MBAR_ARRIVE_DEP(fre, bl[1][3]);  // stage read complete for this warp
        mma_half(ah, al, bh, bl, C);

        if (ci + 2 < 16) {
            MBAR_WAIT(fre, s ? ph_f1 : ph_f0);
            if (s) ph_f1 ^= 1; else ph_f0 ^= 1;
            const int kt = (ci + 2) * 32;
            ldg_128x32(st + OFF_AH, Ahi, ld2, kt); ldg_128x32(st + OFF_AL, Alo, ld2, kt);
            ldg_128x32(st + OFF_BH, Bhi, ld2, kt); ldg_128x32(st + OFF_BL, Blo, ld2, kt);
            CPA_MBAR(rdy);
        }
        s ^= 1;
    }
}

// ---------------------------------------------------------------------------
// Fused K1+K3: blocks [0,1024) do qk tiles, blocks [1024,1536) do v tiles.
// ---------------------------------------------------------------------------
__global__ __launch_bounds__(NTHR, 2) void k_qkv(int h, const int* __restrict__ et,
                                                 const float* __restrict__ bias) {
    extern __shared__ char smem[];
    const uint32_t sb = (uint32_t)__cvta_generic_to_shared(smem);
    const int flat = blockIdx.x;
    const int lane = threadIdx.x & 31, wid = threadIdx.x >> 5;
    const int wm = wid >> 2, wn = wid & 3;
    const size_t ld2 = (size_t)DD * 2;

    if (flat < 1024) {
        // ---------------- qk path ----------------
        const int b = flat >> 6, qi = (flat >> 3) & 7, ki = flat & 7;
        const int q0 = qi * 128, k0 = ki * 128;
        const bool below = (k0 < q0);
        if (below && !g_padblk[b * 8 + ki]) return;  // uniform early-out (before any sync)
        const bool above = (k0 > q0);

        pipe_init(sb);

        const char* Ahi = (const char*)g_x_hi + ((size_t)b * SS + q0) * DD * 2;
        const char* Alo = (const char*)g_x_lo + ((size_t)b * SS + q0) * DD * 2;
        const char* Bhi = (const char*)g_x_hi + ((size_t)b * SS + k0) * DD * 2;
        const char* Blo = (const char*)g_x_lo + ((size_t)b * SS + k0) * DD * 2;

        float C[4][4][4];
        zeroC(C);
        mainloop_dense(sb, Ahi, Alo, Bhi, Blo, ld2, C);

        const float invtemp = 0.04419417382415922f;  // 1/sqrt(512)
        float* norm2 = g_norm2 + (size_t)h * BB * SS;

        int kg[4]; bool pad0[4], pad1[4];
#pragma unroll
        for (int nt = 0; nt < 4; nt++) {
            kg[nt] = k0 + wn * 32 + nt * 8 + (lane & 3) * 2;
            pad0[nt] = (__ldg(et + b * SS + kg[nt]) == 0);
            pad1[nt] = (__ldg(et + b * SS + kg[nt] + 1) == 0);
        }
#pragma unroll
        for (int mt = 0; mt < 4; mt++) {
            const int r0 = wm * 64 + mt * 16 + (lane >> 2);
            const int qA = q0 + r0, qB = q0 + r0 + 8;
            float sqA = 0.f, sqB = 0.f;
#pragma unroll
            for (int nt = 0; nt < 4; nt++) {
                float v0 = C[mt][nt][0] * invtemp, v1 = C[mt][nt][1] * invtemp;
                float v2 = C[mt][nt][2] * invtemp, v3 = C[mt][nt][3] * invtemp;
                bool kA0 = above || (kg[nt] > qA) || pad0[nt];
                bool kA1 = above || (kg[nt] + 1 > qA) || pad1[nt];
                bool kB0 = above || (kg[nt] > qB) || pad0[nt];
                bool kB1 = above || (kg[nt] + 1 > qB) || pad1[nt];
                v0 = kA0 ? v0 : 0.f; v1 = kA1 ? v1 : 0.f;
                v2 = kB0 ? v2 : 0.f; v3 = kB1 ? v3 : 0.f;
                sqA = fmaf(v0, v0, fmaf(v1, v1, sqA));
                sqB = fmaf(v2, v2, fmaf(v3, v3, sqB));
                const size_t oA = ((size_t)b * SS + qA) * SS + kg[nt];
                const size_t oB = ((size_t)b * SS + qB) * SS + kg[nt];
                *(uint32_t*)(g_attn_hi + oA) = packsplit_hi(v0, v1);
                *(uint32_t*)(g_attn_lo + oA) = packsplit_lo(v0, v1);
                *(uint32_t*)(g_attn_hi + oB) = packsplit_hi(v2, v3);
                *(uint32_t*)(g_attn_lo + oB) = packsplit_lo(v2, v3);
            }
            sqA += __shfl_xor_sync(0xffffffffu, sqA, 1);
            sqA += __shfl_xor_sync(0xffffffffu, sqA, 2);
            sqB += __shfl_xor_sync(0xffffffffu, sqB, 1);
            sqB += __shfl_xor_sync(0xffffffffu, sqB, 2);
            if ((lane & 3) == 0) {
                atomicAdd(&norm2[b * SS + qA], sqA);
                atomicAdd(&norm2[b * SS + qB], sqB);
            }
        }
    } else {
        // ---------------- v path ----------------
        const int f = flat - 1024;           // 0..511
        const int m0 = (f >> 2) * 128, n0 = (f & 3) * 128;

        pipe_init(sb);

        const char* Ahi = (const char*)g_x_hi + (size_t)m0 * DD * 2;
        const char* Alo = (const char*)g_x_lo + (size_t)m0 * DD * 2;
        const char* Bhi = (const char*)g_w_hi + ((size_t)h * DD * DD + (size_t)n0 * DD) * 2;
        const char* Blo = (const char*)g_w_lo + ((size_t)h * DD * DD + (size_t)n0 * DD) * 2;

        float C[4][4][4];
        zeroC(C);
        mainloop_dense(sb, Ahi, Alo, Bhi, Blo, ld2, C);

        float b0[4], b1[4]; int col[4];
#pragma unroll
        for (int nt = 0; nt < 4; nt++) {
            col[nt] = n0 + wn * 32 + nt * 8 + (lane & 3) * 2;
            b0[nt] = __ldg(bias + col[nt]);
            b1[nt] = __ldg(bias + col[nt] + 1);
        }
#pragma unroll
        for (int mt = 0; mt < 4; mt++) {
            const int r0 = wm * 64 + mt * 16 + (lane >> 2);
            const size_t mA = (size_t)(m0 + r0), mB = mA + 8;
#pragma unroll
            for (int nt = 0; nt < 4; nt++) {
                float v0 = C[mt][nt][0] + b0[nt], v1 = C[mt][nt][1] + b1[nt];
                float v2 = C[mt][nt][2] + b0[nt], v3 = C[mt][nt][3] + b1[nt];
                v0 = (v0 > 0.f) ? v0 : expm1f(v0);
                v1 = (v1 > 0.f) ? v1 : expm1f(v1);
                v2 = (v2 > 0.f) ? v2 : expm1f(v2);
                v3 = (v3 > 0.f) ? v3 : expm1f(v3);
                const size_t oA = mA * DD + col[nt], oB = mB * DD + col[nt];
                *(uint32_t*)(g_v_hi + oA) = packsplit_hi(v0, v1);
                *(uint32_t*)(g_v_lo + oA) = packsplit_lo(v0, v1);
                *(uint32_t*)(g_v_hi + oB) = packsplit_hi(v2, v3);
                *(uint32_t*)(g_v_lo + oB) = packsplit_lo(v2, v3);
            }
        }
    }
}

// ---------------------------------------------------------------------------
// K4: xnew = invnorm * (attn · v); mbarrier pipeline with chunk skipping.
// ---------------------------------------------------------------------------
__global__ __launch_bounds__(NTHR, 2) void k_av(int h, float* __restrict__ out) {
    const int b = blockIdx.z, q0 = blockIdx.y * 128, n0 = blockIdx.x * 128;
    extern __shared__ char smem[];
    const uint32_t sb = (uint32_t)__cvta_generic_to_shared(smem);
    const int lane = threadIdx.x & 31;

    pipe_init(sb);

    const char* Ahi = (const char*)g_attn_hi + ((size_t)b * SS + q0) * SS * 2;
    const char* Alo = (const char*)g_attn_lo + ((size_t)b * SS + q0) * SS * 2;
    const char* Bhi = (const char*)g_v_hi + ((size_t)b * SS * DD + n0) * 2;
    const char* Blo = (const char*)g_v_lo + ((size_t)b * SS * DD + n0) * 2;
    const size_t lda2 = (size_t)SS * 2, ldb2 = (size_t)DD * 2;
    const int* p32 = g_pad32 + b * (SS / 32);

    float C[4][4][4];
    zeroC(C);

    // chunk iterator with skipping (below-diagonal, no-pad chunks are all-zero)
    int kt0 = 0;
    while (kt0 + 32 <= q0 && !p32[kt0 >> 5]) kt0 += 32;
    int kt1 = kt0 + 32;
    while (kt1 < SS && kt1 + 32 <= q0 && !p32[kt1 >> 5]) kt1 += 32;

    // prologue loads
    ldg_128x32(sb + OFF_AH, Ahi, lda2, kt0); ldg_128x32(sb + OFF_AL, Alo, lda2, kt0);
    ldg_32x128(sb + OFF_BH, Bhi, ldb2, kt0); ldg_32x128(sb + OFF_BL, Blo, ldb2, kt0);
    CPA_MBAR(sb + MB_READY0);
    if (kt1 < SS) {
        ldg_128x32(sb + ST_SZ + OFF_AH, Ahi, lda2, kt1); ldg_128x32(sb + ST_SZ + OFF_AL, Alo, lda2, kt1);
        ldg_32x128(sb + ST_SZ + OFF_BH, Bhi, ldb2, kt1); ldg_32x128(sb + ST_SZ + OFF_BL, Blo, ldb2, kt1);
        CPA_MBAR(sb + MB_READY1);
    }

    uint32_t ah[4][4], al[4][4], bh[2][4], bl[2][4];
    int ph_r0 = 0, ph_r1 = 0, ph_f0 = 0, ph_f1 = 0;
    int s = 0;
    while (kt0 < SS) {
        const uint32_t st = sb + s * ST_SZ;
        const uint32_t rdy = sb + (s ? MB_READY1 : MB_READY0);
        const uint32_t fre = sb + (s ? MB_FREE1 : MB_FREE0);
        MBAR_WAIT(rdy, s ? ph_r1 : ph_r0);
        if (s) ph_r1 ^= 1; else ph_r0 ^= 1;

        ldsm_half<true>(st, 0, ah, al, bh, bl);
        mma_half(ah, al, bh, bl, C);
        ldsm_half<true>(st, 1, ah, al, bh, bl);
        if (lane == 0) MBAR_ARRIVE_DEP(fre, bl[1][3]);
        mma_half(ah, al, bh, bl, C);

        int kt2 = SS;
        if (kt1 < SS) {
            kt2 = kt1 + 32;
            while (kt2 < SS && kt2 + 32 <= q0 && !p32[kt2 >> 5]) kt2 += 32;
            if (kt2 < SS) {
                MBAR_WAIT(fre, s ? ph_f1 : ph_f0);
                if (s) ph_f1 ^= 1; else ph_f0 ^= 1;
                ldg_128x32(st + OFF_AH, Ahi, lda2, kt2); ldg_128x32(st + OFF_AL, Alo, lda2, kt2);
                ldg_32x128(st + OFF_BH, Bhi, ldb2, kt2); ldg_32x128(st + OFF_BL, Blo, ldb2, kt2);
                CPA_MBAR(rdy);
            }
        }
        kt0 = kt1;
        kt1 = kt2;
        s ^= 1;
    }

    const int wid = threadIdx.x >> 5;
    const int wm = wid >> 2, wn = wid & 3;
    const float* norm2 = g_norm2 + (size_t)h * BB * SS;
#pragma unroll
    for (int mt = 0; mt < 4; mt++) {
        const int r0 = wm * 64 + mt * 16 + (lane >> 2);
        const int qA = q0 + r0, qB = qA + 8;
        const float invA = 1.f / fmaxf(sqrtf(norm2[b * SS + qA]), 1e-5f);
        const float invB = 1.f / fmaxf(sqrtf(norm2[b * SS + qB]), 1e-5f);
#pragma unroll
        for (int nt = 0; nt < 4; nt++) {
            const int col = n0 + wn * 32 + nt * 8 + (lane & 3) * 2;
            float v0 = C[mt][nt][0] * invA, v1 = C[mt][nt][1] * invA;
            float v2 = C[mt][nt][2] * invB, v3 = C[mt][nt][3] * invB;
            const size_t oA = ((size_t)b * SS + qA) * DD + col;
            const size_t oB = ((size_t)b * SS + qB) * DD + col;
            *(uint32_t*)(g_x_hi + oA) = packsplit_hi(v0, v1);
            *(uint32_t*)(g_x_lo + oA) = packsplit_lo(v0, v1);
            *(uint32_t*)(g_x_hi + oB) = packsplit_hi(v2, v3);
            *(uint32_t*)(g_x_lo + oB) = packsplit_lo(v2, v3);
            float2* opA = (float2*)(out + oA);
            float2* opB = (float2*)(out + oB);
            float2 a = *opA; a.x += v0; a.y += v1; *opA = a;
            float2 c = *opB; c.x += v2; c.y += v3; *opB = c;
        }
    }
}

// ---------------------------------------------------------------------------
// setup kernels (2 launches, vectorized: 4 elems/thread)
// ---------------------------------------------------------------------------
__global__ void k_setup1(const float4* __restrict__ x_in, const float4* __restrict__ W) {
    const size_t NX4 = ((size_t)BB * SS * DD) / 4;      // 2,097,152
    size_t i = (size_t)blockIdx.x * NTHR + threadIdx.x; // < 2,359,296
    float4 v;
    uint32_t* dh;
    uint32_t* dl;
    if (i < NX4) {
        v = x_in[i];
        dh = (uint32_t*)(g_x_hi + i * 4);
        dl = (uint32_t*)(g_x_lo + i * 4);
    } else {
        size_t k = i - NX4;
        v = W[k];
        dh = (uint32_t*)(g_w_hi + k * 4);
        dl = (uint32_t*)(g_w_lo + k * 4);
    }
    dh[0] = packsplit_hi(v.x, v.y);
    dh[1] = packsplit_hi(v.z, v.w);
    dl[0] = packsplit_lo(v.x, v.y);
    dl[1] = packsplit_lo(v.z, v.w);
}
__global__ void k_setup2(const int* __restrict__ et, float4* __restrict__ out4) {
    size_t i = (size_t)blockIdx.x * NTHR + threadIdx.x;
    out4[i] = make_float4(0.f, 0.f, 0.f, 0.f);          // 2M float4 = 8.4M floats
    if (i < (HH * BB * SS) / 4)
        ((float4*)g_norm2)[i] = make_float4(0.f, 0.f, 0.f, 0.f);
    if (i < BB * (SS / 32)) {                           // 512 pad32 flags
        int b = (int)(i >> 5), cc = (int)(i & 31);
        int any = 0;
        const int4* p = (const int4*)(et + b * SS + cc * 32);
#pragma unroll
        for (int t = 0; t < 8; t++) {
            int4 e = p[t];
            any |= (e.x == 0) | (e.y == 0) | (e.z == 0) | (e.w == 0);
        }
        g_pad32[i] = any;
    }
    if (i >= 1024 && i < 1024 + BB * (SS / 128)) {      // 128 padblk flags (from et)
        int idx = (int)(i - 1024);
        int b = idx >> 3, kb = idx & 7;
        int any = 0;
        const int4* p = (const int4*)(et + b * SS + kb * 128);
#pragma unroll
        for (int t = 0; t < 32; t++) {
            int4 e = p[t];
            any |= (e.x == 0) | (e.y == 0) | (e.z == 0) | (e.w == 0);
        }
        g_padblk[idx] = any;
    }
}

// ---------------------------------------------------------------------------
extern "C" void kernel_launch(void* const* d_in, const int* in_sizes, int n_in,
                              void* d_out, int out_size) {
    const float* x_in = (const float*)d_in[0];   // [B,S,D] fp32
    const int* et = (const int*)d_in[2];         // [B,S] int32
    const float* W = (const float*)d_in[3];      // [H,D,D] fp32
    const float* bias = (const float*)d_in[4];   // [H,D] fp32
    float* out = (float*)d_out;

    static int configured = 0;
    if (!configured) {
        cudaFuncSetAttribute(k_qkv, cudaFuncAttributeMaxDynamicSharedMemorySize, SMEM_TOT);
        cudaFuncSetAttribute(k_av,  cudaFuncAttributeMaxDynamicSharedMemorySize, SMEM_TOT);
        configured = 1;
    }

    k_setup1<<<9216, NTHR>>>((const float4*)x_in, (const float4*)W);
    k_setup2<<<8192, NTHR>>>(et, (float4*)out);

    const dim3 grid_av(4, 8, BB);
    for (int h = 0; h < HH; h++) {
        k_qkv<<<1536, NTHR, SMEM_TOT>>>(h, et, bias + (size_t)h * DD);
        k_av<<<grid_av, NTHR, SMEM_TOT>>>(h, out);
    }
}

// round 17
// speedup vs baseline: 1.5130x; 1.0445x over previous
#include <cuda_runtime.h>
#include <cuda_bf16.h>
#include <math.h>
#include <stdint.h>

// Problem constants
#define BB 16
#define SS 1024
#define DD 512
#define HH 4
#define NTHR 256

// smem staging: per stage 4 tiles (A hi/lo 128x(32+8)bf16, B hi/lo)
#define ST_SZ  40960
#define OFF_AH 0
#define OFF_AL 10240
#define OFF_BH 20480
#define OFF_BL 30720
// mbarriers after the two stages
#define MB_READY0 (2 * ST_SZ)
#define MB_READY1 (MB_READY0 + 8)
#define MB_FREE0  (MB_READY0 + 16)
#define MB_FREE1  (MB_READY0 + 24)
#define SMEM_TOT  (MB_READY0 + 32)

#define STRA 80    // bytes per A/B-NT smem row (40 bf16)
#define STRB 272   // bytes per B-NN smem row (136 bf16)

// ---------------- device scratch ----------------
__device__ __align__(16) __nv_bfloat16 g_x_hi[(size_t)BB*SS*DD];
__device__ __align__(16) __nv_bfloat16 g_x_lo[(size_t)BB*SS*DD];
__device__ __align__(16) __nv_bfloat16 g_v_hi[(size_t)BB*SS*DD];
__device__ __align__(16) __nv_bfloat16 g_v_lo[(size_t)BB*SS*DD];
__device__ __align__(16) __nv_bfloat16 g_attn_hi[(size_t)BB*SS*SS];
__device__ __align__(16) __nv_bfloat16 g_attn_lo[(size_t)BB*SS*SS];
__device__ __align__(16) __nv_bfloat16 g_w_hi[(size_t)HH*DD*DD];
__device__ __align__(16) __nv_bfloat16 g_w_lo[(size_t)HH*DD*DD];
__device__ __align__(16) float g_norm2[HH * BB * SS];
__device__ int g_pad32[BB*(SS/32)];
__device__ int g_padblk[BB*(SS/128)];

// ---------------- PTX helpers (sm_80/90 base ISA; harness targets plain sm_103) ----
#define CPA16(s, g) asm volatile("cp.async.cg.shared.global [%0], [%1], 16;" :: "r"(s), "l"(g))
#define CPA_MBAR(a) asm volatile("cp.async.mbarrier.arrive.noinc.shared.b64 [%0];" :: "r"(a) : "memory")
#define MBAR_INIT(a, n) asm volatile("mbarrier.init.shared.b64 [%0], %1;" :: "r"(a), "r"(n) : "memory")
// arrive with a dummy data dependency: orders the arrive after the producing ldsm
#define MBAR_ARRIVE_DEP(a, dep)                                                \
    asm volatile("{\n\t.reg .b64 t;\n\tmbarrier.arrive.shared.b64 t, [%0];\n\t}" \
                 :: "r"(a), "r"(dep) : "memory")
#define MBAR_WAIT(addr, ph) do {                                               \
    uint32_t _m = (addr), _p = (uint32_t)(ph), _d;                             \
    asm volatile("{\n\t.reg .pred p;\n\t"                                      \
        "mbarrier.try_wait.parity.acquire.cta.shared::cta.b64 p, [%1], %2;\n\t" \
        "selp.b32 %0, 1, 0, p;\n\t}" : "=r"(_d) : "r"(_m), "r"(_p) : "memory"); \
    if (!_d) {                                                                 \
        asm volatile("{\n\t.reg .pred P1;\n\tWL_%=:\n\t"                       \
            "mbarrier.try_wait.parity.acquire.cta.shared::cta.b64 P1, [%0], %1, 0x989680;\n\t" \
            "@P1 bra.uni WD_%=;\n\tbra.uni WL_%=;\n\tWD_%=:\n\t}"              \
            :: "r"(_m), "r"(_p) : "memory");                                   \
    }                                                                          \
} while (0)

#define LDSMX4(r0, r1, r2, r3, a)                                              \
    asm volatile("ldmatrix.sync.aligned.m8n8.x4.shared.b16 {%0,%1,%2,%3}, [%4];" \
                 : "=r"(r0), "=r"(r1), "=r"(r2), "=r"(r3) : "r"(a))
#define LDSMX4T(r0, r1, r2, r3, a)                                             \
    asm volatile("ldmatrix.sync.aligned.m8n8.x4.trans.shared.b16 {%0,%1,%2,%3}, [%4];" \
                 : "=r"(r0), "=r"(r1), "=r"(r2), "=r"(r3) : "r"(a))

#define MMA16816(c, a, b0v, b1v)                                               \
    asm volatile(                                                              \
        "mma.sync.aligned.m16n8k16.row.col.f32.bf16.bf16.f32 "                 \
        "{%0,%1,%2,%3}, {%4,%5,%6,%7}, {%8,%9}, {%0,%1,%2,%3};"                \
        : "+f"((c)[0]), "+f"((c)[1]), "+f"((c)[2]), "+f"((c)[3])               \
        : "r"((a)[0]), "r"((a)[1]), "r"((a)[2]), "r"((a)[3]), "r"(b0v), "r"(b1v))

// ---------------- tile loaders (256 threads) ----------------
__device__ __forceinline__ void ldg_128x32(uint32_t dst, const char* src, size_t ld2, int kt) {
#pragma unroll
    for (int p = 0; p < 2; p++) {
        int i = threadIdx.x + p * NTHR;
        int row = i >> 2, seg = i & 3;
        CPA16(dst + row * STRA + seg * 16,
              src + (size_t)row * ld2 + (size_t)kt * 2 + seg * 16);
    }
}
__device__ __forceinline__ void ldg_32x128(uint32_t dst, const char* src, size_t ld2, int kt) {
#pragma unroll
    for (int p = 0; p < 2; p++) {
        int i = threadIdx.x + p * NTHR;
        int row = i >> 4, seg = i & 15;
        CPA16(dst + row * STRB + seg * 16,
              src + (size_t)(kt + row) * ld2 + seg * 16);
    }
}

// ---------------- ldsm / mma halves (one ks of a 128x128x32 chunk) ----------
template <bool BT>
__device__ __forceinline__ void ldsm_half(uint32_t sbase, int ks,
                                          uint32_t (&ah)[4][4], uint32_t (&al)[4][4],
                                          uint32_t (&bh)[2][4], uint32_t (&bl)[2][4]) {
    const int lane = threadIdx.x & 31;
    const int wid = threadIdx.x >> 5;
    const int wm = wid >> 2, wn = wid & 3;
#pragma unroll
    for (int mt = 0; mt < 4; mt++) {
        uint32_t ra = sbase + OFF_AH +
            (uint32_t)((wm * 64 + mt * 16 + (lane & 15)) * STRA + ks * 32 + (lane >> 4) * 16);
        LDSMX4(ah[mt][0], ah[mt][1], ah[mt][2], ah[mt][3], ra);
        ra += (OFF_AL - OFF_AH);
        LDSMX4(al[mt][0], al[mt][1], al[mt][2], al[mt][3], ra);
    }
#pragma unroll
    for (int ntp = 0; ntp < 2; ntp++) {
        if (!BT) {
            uint32_t rb = sbase + OFF_BH +
                (uint32_t)((wn * 32 + ntp * 16 + (lane >> 4) * 8 + (lane & 7)) * STRA +
                           ks * 32 + ((lane >> 3) & 1) * 16);
            LDSMX4(bh[ntp][0], bh[ntp][1], bh[ntp][2], bh[ntp][3], rb);
            rb += (OFF_BL - OFF_BH);
            LDSMX4(bl[ntp][0], bl[ntp][1], bl[ntp][2], bl[ntp][3], rb);
        } else {
            uint32_t rb = sbase + OFF_BH +
                (uint32_t)((ks * 16 + ((lane >> 3) & 1) * 8 + (lane & 7)) * STRB +
                           (wn * 32 + ntp * 16) * 2 + (lane >> 4) * 16);
            LDSMX4T(bh[ntp][0], bh[ntp][1], bh[ntp][2], bh[ntp][3], rb);
            rb += (OFF_BL - OFF_BH);
            LDSMX4T(bl[ntp][0], bl[ntp][1], bl[ntp][2], bl[ntp][3], rb);
        }
    }
}
__device__ __forceinline__ void mma_half(const uint32_t (&ah)[4][4], const uint32_t (&al)[4][4],
                                         const uint32_t (&bh)[2][4], const uint32_t (&bl)[2][4],
                                         float (&C)[4][4][4]) {
#pragma unroll
    for (int mt = 0; mt < 4; mt++)
#pragma unroll
        for (int nt = 0; nt < 4; nt++) {
            const int p = nt >> 1, j = (nt & 1) * 2;
            MMA16816(C[mt][nt], ah[mt], bh[p][j], bh[p][j + 1]);
            MMA16816(C[mt][nt], ah[mt], bl[p][j], bl[p][j + 1]);
            MMA16816(C[mt][nt], al[mt], bh[p][j], bh[p][j + 1]);
        }
}

__device__ __forceinline__ void zeroC(float (&C)[4][4][4]) {
#pragma unroll
    for (int a = 0; a < 4; a++)
#pragma unroll
        for (int b = 0; b < 4; b++)
#pragma unroll
            for (int c = 0; c < 4; c++) C[a][b][c] = 0.f;
}
__device__ __forceinline__ uint32_t packsplit_hi(float v0, float v1) {
    __nv_bfloat162 h = __floats2bfloat162_rn(v0, v1);
    return *(uint32_t*)&h;
}
__device__ __forceinline__ uint32_t packsplit_lo(float v0, float v1) {
    float r0 = v0 - __bfloat162float(__float2bfloat16(v0));
    float r1 = v1 - __bfloat162float(__float2bfloat16(v1));
    __nv_bfloat162 l = __floats2bfloat162_rn(r0, r1);
    return *(uint32_t*)&l;
}

// init the 4 pipeline mbarriers; one __syncthreads total
__device__ __forceinline__ void pipe_init(uint32_t sb) {
    if (threadIdx.x == 0) {
        MBAR_INIT(sb + MB_READY0, NTHR);
        MBAR_INIT(sb + MB_READY1, NTHR);
        MBAR_INIT(sb + MB_FREE0, 8);
        MBAR_INIT(sb + MB_FREE1, 8);
    }
    __syncthreads();
}

// dense-K 16-chunk mbarrier-pipelined mainloop (both operands NT 128x32 tiles)
__device__ __forceinline__ void mainloop_dense(uint32_t sb,
                                               const char* Ahi, const char* Alo,
                                               const char* Bhi, const char* Blo,
                                               size_t ld2, float (&C)[4][4][4]) {
    const int lane = threadIdx.x & 31;
    // prologue: chunk0 -> stage0, chunk1 -> stage1
    ldg_128x32(sb + OFF_AH, Ahi, ld2, 0); ldg_128x32(sb + OFF_AL, Alo, ld2, 0);
    ldg_128x32(sb + OFF_BH, Bhi, ld2, 0); ldg_128x32(sb + OFF_BL, Blo, ld2, 0);
    CPA_MBAR(sb + MB_READY0);
    ldg_128x32(sb + ST_SZ + OFF_AH, Ahi, ld2, 32); ldg_128x32(sb + ST_SZ + OFF_AL, Alo, ld2, 32);
    ldg_128x32(sb + ST_SZ + OFF_BH, Bhi, ld2, 32); ldg_128x32(sb + ST_SZ + OFF_BL, Blo, ld2, 32);
    CPA_MBAR(sb + MB_READY1);

    uint32_t ah[4][4], al[4][4], bh[2][4], bl[2][4];
    int ph_r0 = 0, ph_r1 = 0, ph_f0 = 0, ph_f1 = 0;
    int s = 0;
    for (int ci = 0; ci < 16; ci++) {
        const uint32_t st = sb + s * ST_SZ;
        const uint32_t rdy = sb + (s ? MB_READY1 : MB_READY0);
        const uint32_t fre = sb + (s ? MB_FREE1 : MB_FREE0);
        MBAR_WAIT(rdy, s ? ph_r1 : ph_r0);
        if (s) ph_r1 ^= 1; else ph_r0 ^= 1;

        ldsm_half<false>(st, 0, ah, al, bh, bl);
        mma_half(ah, al, bh, bl, C);
        ldsm_half<false>(st, 1, ah, al, bh, bl);
        if (lane == 0) MBAR_ARRIVE_DEP(fre, bl[1][3]);  // stage read complete for this warp
        mma_half(ah, al, bh, bl, C);

        if (ci + 2 < 16) {
            MBAR_WAIT(fre, s ? ph_f1 : ph_f0);
            if (s) ph_f1 ^= 1; else ph_f0 ^= 1;
            const int kt = (ci + 2) * 32;
            ldg_128x32(st + OFF_AH, Ahi, ld2, kt); ldg_128x32(st + OFF_AL, Alo, ld2, kt);
            ldg_128x32(st + OFF_BH, Bhi, ld2, kt); ldg_128x32(st + OFF_BL, Blo, ld2, kt);
            CPA_MBAR(rdy);
        }
        s ^= 1;
    }
}

// ---------------------------------------------------------------------------
// Fused K1+K3: blocks [0,1024) do qk tiles, blocks [1024,1536) do v tiles.
// ---------------------------------------------------------------------------
__global__ __launch_bounds__(NTHR, 2) void k_qkv(int h, const int* __restrict__ et,
                                                 const float* __restrict__ bias) {
    extern __shared__ char smem[];
    const uint32_t sb = (uint32_t)__cvta_generic_to_shared(smem);
    const int flat = blockIdx.x;
    const int lane = threadIdx.x & 31, wid = threadIdx.x >> 5;
    const int wm = wid >> 2, wn = wid & 3;
    const size_t ld2 = (size_t)DD * 2;

    if (flat < 1024) {
        // ---------------- qk path ----------------
        const int b = flat >> 6, qi = (flat >> 3) & 7, ki = flat & 7;
        const int q0 = qi * 128, k0 = ki * 128;
        const bool below = (k0 < q0);
        if (below && !g_padblk[b * 8 + ki]) return;  // uniform early-out (before any sync)
        const bool above = (k0 > q0);

        pipe_init(sb);

        const char* Ahi = (const char*)g_x_hi + ((size_t)b * SS + q0) * DD * 2;
        const char* Alo = (const char*)g_x_lo + ((size_t)b * SS + q0) * DD * 2;
        const char* Bhi = (const char*)g_x_hi + ((size_t)b * SS + k0) * DD * 2;
        const char* Blo = (const char*)g_x_lo + ((size_t)b * SS + k0) * DD * 2;

        float C[4][4][4];
        zeroC(C);
        mainloop_dense(sb, Ahi, Alo, Bhi, Blo, ld2, C);

        const float invtemp = 0.04419417382415922f;  // 1/sqrt(512)
        float* norm2 = g_norm2 + (size_t)h * BB * SS;

        int kg[4]; bool pad0[4], pad1[4];
#pragma unroll
        for (int nt = 0; nt < 4; nt++) {
            kg[nt] = k0 + wn * 32 + nt * 8 + (lane & 3) * 2;
            pad0[nt] = (__ldg(et + b * SS + kg[nt]) == 0);
            pad1[nt] = (__ldg(et + b * SS + kg[nt] + 1) == 0);
        }
#pragma unroll
        for (int mt = 0; mt < 4; mt++) {
            const int r0 = wm * 64 + mt * 16 + (lane >> 2);
            const int qA = q0 + r0, qB = q0 + r0 + 8;
            float sqA = 0.f, sqB = 0.f;
#pragma unroll
            for (int nt = 0; nt < 4; nt++) {
                float v0 = C[mt][nt][0] * invtemp, v1 = C[mt][nt][1] * invtemp;
                float v2 = C[mt][nt][2] * invtemp, v3 = C[mt][nt][3] * invtemp;
                bool kA0 = above || (kg[nt] > qA) || pad0[nt];
                bool kA1 = above || (kg[nt] + 1 > qA) || pad1[nt];
                bool kB0 = above || (kg[nt] > qB) || pad0[nt];
                bool kB1 = above || (kg[nt] + 1 > qB) || pad1[nt];
                v0 = kA0 ? v0 : 0.f; v1 = kA1 ? v1 : 0.f;
                v2 = kB0 ? v2 : 0.f; v3 = kB1 ? v3 : 0.f;
                sqA = fmaf(v0, v0, fmaf(v1, v1, sqA));
                sqB = fmaf(v2, v2, fmaf(v3, v3, sqB));
                const size_t oA = ((size_t)b * SS + qA) * SS + kg[nt];
                const size_t oB = ((size_t)b * SS + qB) * SS + kg[nt];
                *(uint32_t*)(g_attn_hi + oA) = packsplit_hi(v0, v1);
                *(uint32_t*)(g_attn_lo + oA) = packsplit_lo(v0, v1);
                *(uint32_t*)(g_attn_hi + oB) = packsplit_hi(v2, v3);
                *(uint32_t*)(g_attn_lo + oB) = packsplit_lo(v2, v3);
            }
            sqA += __shfl_xor_sync(0xffffffffu, sqA, 1);
            sqA += __shfl_xor_sync(0xffffffffu, sqA, 2);
            sqB += __shfl_xor_sync(0xffffffffu, sqB, 1);
            sqB += __shfl_xor_sync(0xffffffffu, sqB, 2);
            if ((lane & 3) == 0) {
                atomicAdd(&norm2[b * SS + qA], sqA);
                atomicAdd(&norm2[b * SS + qB], sqB);
            }
        }
    } else {
        // ---------------- v path ----------------
        const int f = flat - 1024;           // 0..511
        const int m0 = (f >> 2) * 128, n0 = (f & 3) * 128;

        pipe_init(sb);

        const char* Ahi = (const char*)g_x_hi + (size_t)m0 * DD * 2;
        const char* Alo = (const char*)g_x_lo + (size_t)m0 * DD * 2;
        const char* Bhi = (const char*)g_w_hi + ((size_t)h * DD * DD + (size_t)n0 * DD) * 2;
        const char* Blo = (const char*)g_w_lo + ((size_t)h * DD * DD + (size_t)n0 * DD) * 2;

        float C[4][4][4];
        zeroC(C);
        mainloop_dense(sb, Ahi, Alo, Bhi, Blo, ld2, C);

        float b0[4], b1[4]; int col[4];
#pragma unroll
        for (int nt = 0; nt < 4; nt++) {
            col[nt] = n0 + wn * 32 + nt * 8 + (lane & 3) * 2;
            b0[nt] = __ldg(bias + col[nt]);
            b1[nt] = __ldg(bias + col[nt] + 1);
        }
#pragma unroll
        for (int mt = 0; mt < 4; mt++) {
            const int r0 = wm * 64 + mt * 16 + (lane >> 2);
            const size_t mA = (size_t)(m0 + r0), mB = mA + 8;
#pragma unroll
            for (int nt = 0; nt < 4; nt++) {
                float v0 = C[mt][nt][0] + b0[nt], v1 = C[mt][nt][1] + b1[nt];
                float v2 = C[mt][nt][2] + b0[nt], v3 = C[mt][nt][3] + b1[nt];
                v0 = (v0 > 0.f) ? v0 : expm1f(v0);
                v1 = (v1 > 0.f) ? v1 : expm1f(v1);
                v2 = (v2 > 0.f) ? v2 : expm1f(v2);
                v3 = (v3 > 0.f) ? v3 : expm1f(v3);
                const size_t oA = mA * DD + col[nt], oB = mB * DD + col[nt];
                *(uint32_t*)(g_v_hi + oA) = packsplit_hi(v0, v1);
                *(uint32_t*)(g_v_lo + oA) = packsplit_lo(v0, v1);
                *(uint32_t*)(g_v_hi + oB) = packsplit_hi(v2, v3);
                *(uint32_t*)(g_v_lo + oB) = packsplit_lo(v2, v3);
            }
        }
    }
}

// ---------------------------------------------------------------------------
// K4: xnew = invnorm * (attn · v); mbarrier pipeline with chunk skipping.
// 1D grid, heavy tiles (high qi, long K) scheduled FIRST to cut the wave tail.
// ---------------------------------------------------------------------------
__global__ __launch_bounds__(NTHR, 2) void k_av(int h, float* __restrict__ out) {
    // heavy-first mapping: qi descends with blockIdx.x
    const int idx = blockIdx.x;              // 0..511
    const int qi = 7 - (idx >> 6);           // 64 blocks per qi, heavy (qi=7) first
    const int rest = idx & 63;
    const int b = rest >> 2;
    const int n0 = (rest & 3) * 128;
    const int q0 = qi * 128;

    extern __shared__ char smem[];
    const uint32_t sb = (uint32_t)__cvta_generic_to_shared(smem);
    const int lane = threadIdx.x & 31;

    pipe_init(sb);

    const char* Ahi = (const char*)g_attn_hi + ((size_t)b * SS + q0) * SS * 2;
    const char* Alo = (const char*)g_attn_lo + ((size_t)b * SS + q0) * SS * 2;
    const char* Bhi = (const char*)g_v_hi + ((size_t)b * SS * DD + n0) * 2;
    const char* Blo = (const char*)g_v_lo + ((size_t)b * SS * DD + n0) * 2;
    const size_t lda2 = (size_t)SS * 2, ldb2 = (size_t)DD * 2;
    const int* p32 = g_pad32 + b * (SS / 32);

    float C[4][4][4];
    zeroC(C);

    // chunk iterator with skipping (below-diagonal, no-pad chunks are all-zero)
    int kt0 = 0;
    while (kt0 + 32 <= q0 && !p32[kt0 >> 5]) kt0 += 32;
    int kt1 = kt0 + 32;
    while (kt1 < SS && kt1 + 32 <= q0 && !p32[kt1 >> 5]) kt1 += 32;

    // prologue loads
    ldg_128x32(sb + OFF_AH, Ahi, lda2, kt0); ldg_128x32(sb + OFF_AL, Alo, lda2, kt0);
    ldg_32x128(sb + OFF_BH, Bhi, ldb2, kt0); ldg_32x128(sb + OFF_BL, Blo, ldb2, kt0);
    CPA_MBAR(sb + MB_READY0);
    if (kt1 < SS) {
        ldg_128x32(sb + ST_SZ + OFF_AH, Ahi, lda2, kt1); ldg_128x32(sb + ST_SZ + OFF_AL, Alo, lda2, kt1);
        ldg_32x128(sb + ST_SZ + OFF_BH, Bhi, ldb2, kt1); ldg_32x128(sb + ST_SZ + OFF_BL, Blo, ldb2, kt1);
        CPA_MBAR(sb + MB_READY1);
    }

    uint32_t ah[4][4], al[4][4], bh[2][4], bl[2][4];
    int ph_r0 = 0, ph_r1 = 0, ph_f0 = 0, ph_f1 = 0;
    int s = 0;
    while (kt0 < SS) {
        const uint32_t st = sb + s * ST_SZ;
        const uint32_t rdy = sb + (s ? MB_READY1 : MB_READY0);
        const uint32_t fre = sb + (s ? MB_FREE1 : MB_FREE0);
        MBAR_WAIT(rdy, s ? ph_r1 : ph_r0);
        if (s) ph_r1 ^= 1; else ph_r0 ^= 1;

        ldsm_half<true>(st, 0, ah, al, bh, bl);
        mma_half(ah, al, bh, bl, C);
        ldsm_half<true>(st, 1, ah, al, bh, bl);
        if (lane == 0) MBAR_ARRIVE_DEP(fre, bl[1][3]);
        mma_half(ah, al, bh, bl, C);

        int kt2 = SS;
        if (kt1 < SS) {
            kt2 = kt1 + 32;
            while (kt2 < SS && kt2 + 32 <= q0 && !p32[kt2 >> 5]) kt2 += 32;
            if (kt2 < SS) {
                MBAR_WAIT(fre, s ? ph_f1 : ph_f0);
                if (s) ph_f1 ^= 1; else ph_f0 ^= 1;
                ldg_128x32(st + OFF_AH, Ahi, lda2, kt2); ldg_128x32(st + OFF_AL, Alo, lda2, kt2);
                ldg_32x128(st + OFF_BH, Bhi, ldb2, kt2); ldg_32x128(st + OFF_BL, Blo, ldb2, kt2);
                CPA_MBAR(rdy);
            }
        }
        kt0 = kt1;
        kt1 = kt2;
        s ^= 1;
    }

    const int wid = threadIdx.x >> 5;
    const int wm = wid >> 2, wn = wid & 3;
    const float* norm2 = g_norm2 + (size_t)h * BB * SS;
#pragma unroll
    for (int mt = 0; mt < 4; mt++) {
        const int r0 = wm * 64 + mt * 16 + (lane >> 2);
        const int qA = q0 + r0, qB = qA + 8;
        const float invA = 1.f / fmaxf(sqrtf(norm2[b * SS + qA]), 1e-5f);
        const float invB = 1.f / fmaxf(sqrtf(norm2[b * SS + qB]), 1e-5f);
#pragma unroll
        for (int nt = 0; nt < 4; nt++) {
            const int col = n0 + wn * 32 + nt * 8 + (lane & 3) * 2;
            float v0 = C[mt][nt][0] * invA, v1 = C[mt][nt][1] * invA;
            float v2 = C[mt][nt][2] * invB, v3 = C[mt][nt][3] * invB;
            const size_t oA = ((size_t)b * SS + qA) * DD + col;
            const size_t oB = ((size_t)b * SS + qB) * DD + col;
            *(uint32_t*)(g_x_hi + oA) = packsplit_hi(v0, v1);
            *(uint32_t*)(g_x_lo + oA) = packsplit_lo(v0, v1);
            *(uint32_t*)(g_x_hi + oB) = packsplit_hi(v2, v3);
            *(uint32_t*)(g_x_lo + oB) = packsplit_lo(v2, v3);
            float2* opA = (float2*)(out + oA);
            float2* opB = (float2*)(out + oB);
            float2 a = *opA; a.x += v0; a.y += v1; *opA = a;
            float2 c = *opB; c.x += v2; c.y += v3; *opB = c;
        }
    }
}

// ---------------------------------------------------------------------------
// setup kernels (2 launches, vectorized: 4 elems/thread)
// ---------------------------------------------------------------------------
__global__ void k_setup1(const float4* __restrict__ x_in, const float4* __restrict__ W) {
    const size_t NX4 = ((size_t)BB * SS * DD) / 4;      // 2,097,152
    size_t i = (size_t)blockIdx.x * NTHR + threadIdx.x; // < 2,359,296
    float4 v;
    uint32_t* dh;
    uint32_t* dl;
    if (i < NX4) {
        v = x_in[i];
        dh = (uint32_t*)(g_x_hi + i * 4);
        dl = (uint32_t*)(g_x_lo + i * 4);
    } else {
        size_t k = i - NX4;
        v = W[k];
        dh = (uint32_t*)(g_w_hi + k * 4);
        dl = (uint32_t*)(g_w_lo + k * 4);
    }
    dh[0] = packsplit_hi(v.x, v.y);
    dh[1] = packsplit_hi(v.z, v.w);
    dl[0] = packsplit_lo(v.x, v.y);
    dl[1] = packsplit_lo(v.z, v.w);
}
__global__ void k_setup2(const int* __restrict__ et, float4* __restrict__ out4) {
    size_t i = (size_t)blockIdx.x * NTHR + threadIdx.x;
    out4[i] = make_float4(0.f, 0.f, 0.f, 0.f);          // 2M float4 = 8.4M floats
    if (i < (HH * BB * SS) / 4)
        ((float4*)g_norm2)[i] = make_float4(0.f, 0.f, 0.f, 0.f);
    if (i < BB * (SS / 32)) {                           // 512 pad32 flags
        int b = (int)(i >> 5), cc = (int)(i & 31);
        int any = 0;
        const int4* p = (const int4*)(et + b * SS + cc * 32);
#pragma unroll
        for (int t = 0; t < 8; t++) {
            int4 e = p[t];
            any |= (e.x == 0) | (e.y == 0) | (e.z == 0) | (e.w == 0);
        }
        g_pad32[i] = any;
    }
    if (i >= 1024 && i < 1024 + BB * (SS / 128)) {      // 128 padblk flags (from et)
        int idx = (int)(i - 1024);
        int b = idx >> 3, kb = idx & 7;
        int any = 0;
        const int4* p = (const int4*)(et + b * SS + kb * 128);
#pragma unroll
        for (int t = 0; t < 32; t++) {
            int4 e = p[t];
            any |= (e.x == 0) | (e.y == 0) | (e.z == 0) | (e.w == 0);
        }
        g_padblk[idx] = any;
    }
}

// ---------------------------------------------------------------------------
extern "C" void kernel_launch(void* const* d_in, const int* in_sizes, int n_in,
                              void* d_out, int out_size) {
    const float* x_in = (const float*)d_in[0];   // [B,S,D] fp32
    const int* et = (const int*)d_in[2];         // [B,S] int32
    const float* W = (const float*)d_in[3];      // [H,D,D] fp32
    const float* bias = (const float*)d_in[4];   // [H,D] fp32
    float* out = (float*)d_out;

    static int configured = 0;
    if (!configured) {
        cudaFuncSetAttribute(k_qkv, cudaFuncAttributeMaxDynamicSharedMemorySize, SMEM_TOT);
        cudaFuncSetAttribute(k_av,  cudaFuncAttributeMaxDynamicSharedMemorySize, SMEM_TOT);
        configured = 1;
    }

    k_setup1<<<9216, NTHR>>>((const float4*)x_in, (const float4*)W);
    k_setup2<<<8192, NTHR>>>(et, (float4*)out);

    for (int h = 0; h < HH; h++) {
        k_qkv<<<1536, NTHR, SMEM_TOT>>>(h, et, bias + (size_t)h * DD);
        k_av<<<512, NTHR, SMEM_TOT>>>(h, out);
    }
}